// round 9
// baseline (speedup 1.0000x reference)
#include <cuda_runtime.h>
#include <cuda_bf16.h>
#include <cstdint>

typedef __nv_bfloat16 bf16;

#define KD  512
#define NR  8192
#define CHUNK 1024
#define NCHUNK (NR / CHUNK)
#define NPART (NCHUNK * (CHUNK / 128) * 64)   // 4096

// stage: Ahi[128][40]@0  Alo@5120  Bhi[128][40]@10240  Blo@15360  (elems)
#define STAGE_ELEMS 20480
#define NSTAGE 3
#define SMEMSZ (STAGE_ELEMS * NSTAGE * 2)   // 122880 B
#define MB (1024 * 1024)

// ---- single scratch buffer (81 MB total statics — proven safe) ----
#define OFF_FP_HI  (0 * MB)
#define OFF_FP_LO  (8 * MB)
#define OFF_FS_HI  (16 * MB)
#define OFF_FS_LO  (24 * MB)
#define OFF_S_HI   (0 * MB)
#define OFF_S_LO   (16 * MB)
#define OFF_WT_HI  (32 * MB)
#define OFF_WT_LO  (32 * MB + 512 * 1024)
#define OFF_HP_HI  (33 * MB)
#define OFF_HP_LO  (41 * MB)
#define OFF_HS_HI  (49 * MB)
#define OFF_HS_LO  (57 * MB)
#define OFF_VT_HI  (65 * MB)
#define OFF_VT_LO  (73 * MB)
#define BUF_BYTES  (81 * MB)

__device__ __align__(1024) char g_buf[BUF_BYTES];
__device__ float g_part[NPART];
__device__ float g_scale[1];

// ---------------- helpers ----------------
__device__ __forceinline__ void split_bf(float v, bf16& hi, bf16& lo)
{
    hi = __float2bfloat16(v);
    lo = __float2bfloat16(v - __bfloat162float(hi));
}
__device__ __forceinline__ uint32_t pack2(bf16 a, bf16 b)
{
    return (uint32_t)__bfloat16_as_ushort(a) | ((uint32_t)__bfloat16_as_ushort(b) << 16);
}
__device__ __forceinline__ uint32_t lds_u32(const bf16* p)
{
    return *reinterpret_cast<const uint32_t*>(p);
}
#define MMA_BF16(d, a0, a1, a2, a3, b0, b1)                                   \
    asm volatile(                                                             \
        "mma.sync.aligned.m16n8k16.row.col.f32.bf16.bf16.f32 "                \
        "{%0,%1,%2,%3},{%4,%5,%6,%7},{%8,%9},{%0,%1,%2,%3};"                  \
        : "+f"(d[0]), "+f"(d[1]), "+f"(d[2]), "+f"(d[3])                      \
        : "r"(a0), "r"(a1), "r"(a2), "r"(a3), "r"(b0), "r"(b1))

#define CPA16(dst, src) \
    asm volatile("cp.async.cg.shared.global [%0], [%1], 16;" :: "r"(dst), "l"(src))

// ---------------- elementwise split of feats ----------------
__global__ __launch_bounds__(256) void convert_feats(const float* __restrict__ fp,
                                                     const float* __restrict__ fs)
{
    size_t i = (size_t)blockIdx.x * 256 + threadIdx.x;
    const float4 v = ((const float4*)(blockIdx.y ? fs : fp))[i];
    bf16* Hh = (bf16*)(g_buf + (blockIdx.y ? OFF_FS_HI : OFF_FP_HI));
    bf16* Hl = (bf16*)(g_buf + (blockIdx.y ? OFF_FS_LO : OFF_FP_LO));
    bf16 h0, l0, h1, l1, h2, l2, h3, l3;
    split_bf(v.x, h0, l0); split_bf(v.y, h1, l1);
    split_bf(v.z, h2, l2); split_bf(v.w, h3, l3);
    ((uint2*)Hh)[i] = make_uint2(pack2(h0, h1), pack2(h2, h3));
    ((uint2*)Hl)[i] = make_uint2(pack2(l0, l1), pack2(l2, l3));
}

// ---------------- transpose W (512x512) -> Wt hi/lo ----------------
__global__ void transpose_w(const float* __restrict__ W)
{
    __shared__ float s[32][33];
    int k = blockIdx.y * 32 + threadIdx.y;
    int n = blockIdx.x * 32 + threadIdx.x;
    s[threadIdx.y][threadIdx.x] = W[k * KD + n];
    __syncthreads();
    int nn = blockIdx.x * 32 + threadIdx.y;
    int kk = blockIdx.y * 32 + threadIdx.x;
    float v = s[threadIdx.x][threadIdx.y];
    bf16 h, l; split_bf(v, h, l);
    ((bf16*)(g_buf + OFF_WT_HI))[nn * KD + kk] = h;
    ((bf16*)(g_buf + OFF_WT_LO))[nn * KD + kk] = l;
}

// ---------------- transpose feat_s (8192x512) -> Vt hi/lo (512x8192) ----------
__global__ void transpose_vs(const float* __restrict__ fs)
{
    __shared__ float s[32][33];
    int k = blockIdx.y * 32 + threadIdx.y;
    int n = blockIdx.x * 32 + threadIdx.x;
    s[threadIdx.y][threadIdx.x] = fs[(size_t)k * KD + n];
    __syncthreads();
    int nn = blockIdx.x * 32 + threadIdx.y;
    int kk = blockIdx.y * 32 + threadIdx.x;
    float v = s[threadIdx.x][threadIdx.y];
    bf16 h, l; split_bf(v, h, l);
    ((bf16*)(g_buf + OFF_VT_HI))[(size_t)nn * NR + kk] = h;
    ((bf16*)(g_buf + OFF_VT_LO))[(size_t)nn * NR + kk] = l;
}

// ---------------- unified GEMM: D[128,128] tile = A[128,K] * B[128,K]^T ------
// bf16x3 (hi*hi + hi*lo + lo*hi), two-pass A fragments, 3-stage cp.async.
// warp grid 2x4: warp tile 64x32.
extern __shared__ char s_raw[];

template <int MODE, int LDA, int LDB, int KTILES, int LDO, bool ACCUM>
__global__ __launch_bounds__(256, 1) void gemm_kernel(
    const bf16* __restrict__ Ahi, const bf16* __restrict__ Alo,
    const bf16* __restrict__ Bhi, const bf16* __restrict__ Blo,
    bf16* __restrict__ Ohi, bf16* __restrict__ Olo,
    float* __restrict__ Of, int part_off)
{
    bf16* smbase = (bf16*)s_raw;
    const int tid = threadIdx.x, lane = tid & 31, warp = tid >> 5;
    const int wm = (warp >> 2) * 64;
    const int wn = (warp & 3) * 32;
    const int m0 = blockIdx.y * 128, n0 = blockIdx.x * 128;

    // loader: 128 rows, 2 threads/row, 2x16B per thread per region (8 total)
    const int ra = tid >> 1, ca = (tid & 1) * 16;
    const bf16* pAh = Ahi + (size_t)(m0 + ra) * LDA + ca;
    const bf16* pAl = Alo + (size_t)(m0 + ra) * LDA + ca;
    const bf16* pBh = Bhi + (size_t)(n0 + ra) * LDB + ca;
    const bf16* pBl = Blo + (size_t)(n0 + ra) * LDB + ca;
    const uint32_t sbase = (uint32_t)__cvta_generic_to_shared(smbase);
    const uint32_t oAh = sbase + (uint32_t)(ra * 40 + ca) * 2;
    const uint32_t oAl = oAh + 10240;
    const uint32_t oBh = oAh + 20480;
    const uint32_t oBl = oAh + 30720;

    auto load_stage = [&](int st, int kt) {
        const uint32_t s = (uint32_t)st * (STAGE_ELEMS * 2);
        const int ko = kt * 32;
        CPA16(oAh + s,      pAh + ko);
        CPA16(oAh + s + 16, pAh + ko + 8);
        CPA16(oAl + s,      pAl + ko);
        CPA16(oAl + s + 16, pAl + ko + 8);
        CPA16(oBh + s,      pBh + ko);
        CPA16(oBh + s + 16, pBh + ko + 8);
        CPA16(oBl + s,      pBl + ko);
        CPA16(oBl + s + 16, pBl + ko + 8);
    };

    float acc[4][4][4];
    #pragma unroll
    for (int a = 0; a < 4; a++)
        #pragma unroll
        for (int b = 0; b < 4; b++)
            #pragma unroll
            for (int c = 0; c < 4; c++) acc[a][b][c] = 0.f;

    load_stage(0, 0);
    asm volatile("cp.async.commit_group;");
    load_stage(1, 1);
    asm volatile("cp.async.commit_group;");

    int stage = 0;
    for (int kt = 0; kt < KTILES; kt++) {
        asm volatile("cp.async.wait_group 1;");
        __syncthreads();

        const bf16* sb = smbase + stage * STAGE_ELEMS;
        const bf16* sB = sb + 10240;
        #pragma unroll
        for (int s = 0; s < 2; s++) {
            const int acol = s * 16 + (lane & 3) * 2;
            uint32_t afr[4][4];

            // pass 1: A_hi -> hi*hi + hi*lo
            #pragma unroll
            for (int mi = 0; mi < 4; mi++) {
                const bf16* p = sb + (wm + mi * 16 + (lane >> 2)) * 40 + acol;
                afr[mi][0] = lds_u32(p);
                afr[mi][1] = lds_u32(p + 8 * 40);
                afr[mi][2] = lds_u32(p + 8);
                afr[mi][3] = lds_u32(p + 8 * 40 + 8);
            }
            #pragma unroll
            for (int ni = 0; ni < 4; ni++) {
                const bf16* p = sB + (wn + ni * 8 + (lane >> 2)) * 40 + acol;
                uint32_t bh0 = lds_u32(p), bh1 = lds_u32(p + 8);
                uint32_t bl0 = lds_u32(p + 5120), bl1 = lds_u32(p + 5120 + 8);
                #pragma unroll
                for (int mi = 0; mi < 4; mi++) {
                    MMA_BF16(acc[mi][ni], afr[mi][0], afr[mi][1], afr[mi][2], afr[mi][3], bh0, bh1);
                    MMA_BF16(acc[mi][ni], afr[mi][0], afr[mi][1], afr[mi][2], afr[mi][3], bl0, bl1);
                }
            }

            // pass 2: A_lo -> lo*hi (reuse afr regs)
            #pragma unroll
            for (int mi = 0; mi < 4; mi++) {
                const bf16* p = sb + 5120 + (wm + mi * 16 + (lane >> 2)) * 40 + acol;
                afr[mi][0] = lds_u32(p);
                afr[mi][1] = lds_u32(p + 8 * 40);
                afr[mi][2] = lds_u32(p + 8);
                afr[mi][3] = lds_u32(p + 8 * 40 + 8);
            }
            #pragma unroll
            for (int ni = 0; ni < 4; ni++) {
                const bf16* p = sB + (wn + ni * 8 + (lane >> 2)) * 40 + acol;
                uint32_t bh0 = lds_u32(p), bh1 = lds_u32(p + 8);
                #pragma unroll
                for (int mi = 0; mi < 4; mi++)
                    MMA_BF16(acc[mi][ni], afr[mi][0], afr[mi][1], afr[mi][2], afr[mi][3], bh0, bh1);
            }
        }
        __syncthreads();
        if (kt + 2 < KTILES)
            load_stage((stage + 2) % NSTAGE, kt + 2);   // correct ring slot
        asm volatile("cp.async.commit_group;");
        stage = (stage + 1 == NSTAGE) ? 0 : stage + 1;
    }

    // ---------------- epilogue ----------------
    float s2 = 0.f;
    #pragma unroll
    for (int mi = 0; mi < 4; mi++)
        #pragma unroll
        for (int ni = 0; ni < 4; ni++) {
            const int m = m0 + wm + mi * 16 + (lane >> 2);
            const int n = n0 + wn + ni * 8 + (lane & 3) * 2;
            float v0 = acc[mi][ni][0], v1 = acc[mi][ni][1];
            float v2 = acc[mi][ni][2], v3 = acc[mi][ni][3];
            if constexpr (MODE == 1) {
                v0 = fmaxf(v0, 0.f); v1 = fmaxf(v1, 0.f);
                v2 = fmaxf(v2, 0.f); v3 = fmaxf(v3, 0.f);
                s2 = fmaf(v0, v0, s2); s2 = fmaf(v1, v1, s2);
                s2 = fmaf(v2, v2, s2); s2 = fmaf(v3, v3, s2);
            }
            if constexpr (MODE == 2) {
                float2* p0 = (float2*)&Of[(size_t)m * LDO + n];
                float2* p1 = (float2*)&Of[(size_t)(m + 8) * LDO + n];
                if constexpr (ACCUM) {
                    float2 o0 = *p0, o1 = *p1;
                    *p0 = make_float2(o0.x + v0, o0.y + v1);
                    *p1 = make_float2(o1.x + v2, o1.y + v3);
                } else {
                    *p0 = make_float2(v0, v1);
                    *p1 = make_float2(v2, v3);
                }
            } else {
                bf16 h0, l0, h1, l1;
                split_bf(v0, h0, l0); split_bf(v1, h1, l1);
                *(uint32_t*)&Ohi[(size_t)m * LDO + n] = pack2(h0, h1);
                *(uint32_t*)&Olo[(size_t)m * LDO + n] = pack2(l0, l1);
                split_bf(v2, h0, l0); split_bf(v3, h1, l1);
                *(uint32_t*)&Ohi[(size_t)(m + 8) * LDO + n] = pack2(h0, h1);
                *(uint32_t*)&Olo[(size_t)(m + 8) * LDO + n] = pack2(l0, l1);
            }
        }

    if constexpr (MODE == 1) {
        __syncthreads();
        float* sf = (float*)s_raw;
        sf[tid] = s2;
        __syncthreads();
        #pragma unroll
        for (int off = 128; off > 0; off >>= 1) {
            if (tid < off) sf[tid] += sf[tid + off];
            __syncthreads();
        }
        if (tid == 0) g_part[part_off + blockIdx.y * gridDim.x + blockIdx.x] = sf[0];
    }
}

// ---------------- reduce NPART partials -> 1/fro -----------------------------
__global__ void reduce_kernel()
{
    __shared__ float rs[1024];
    int t = threadIdx.x;
    float v = 0.f;
    #pragma unroll
    for (int i = 0; i < NPART / 1024; i++) v += g_part[t + 1024 * i];
    rs[t] = v;
    __syncthreads();
    #pragma unroll
    for (int off = 512; off > 0; off >>= 1) {
        if (t < off) rs[t] += rs[t + off];
        __syncthreads();
    }
    if (t == 0) g_scale[0] = 1.0f / sqrtf(rs[0]);
}

// ---------------- scale output in place --------------------------------------
__global__ __launch_bounds__(256) void scale_kernel(float* __restrict__ out)
{
    const float s = g_scale[0];
    size_t i = (size_t)blockIdx.x * blockDim.x + threadIdx.x;
    float4* o = (float4*)out;
    float4 v = o[i];
    v.x *= s; v.y *= s; v.z *= s; v.w *= s;
    o[i] = v;
}

// ---------------- launch ----------------
extern "C" void kernel_launch(void* const* d_in, const int* in_sizes, int n_in,
                              void* d_out, int out_size)
{
    (void)in_sizes; (void)n_in; (void)out_size;
    const float* feat_p = (const float*)d_in[0];
    const float* feat_s = (const float*)d_in[1];
    const float* weight = (const float*)d_in[2];
    float* out = (float*)d_out;

    void* basep = nullptr;
    cudaGetSymbolAddress(&basep, g_buf);
    char* base = (char*)basep;
    bf16* Fp_hi = (bf16*)(base + OFF_FP_HI);
    bf16* Fp_lo = (bf16*)(base + OFF_FP_LO);
    bf16* Fs_hi = (bf16*)(base + OFF_FS_HI);
    bf16* Fs_lo = (bf16*)(base + OFF_FS_LO);
    bf16* S_hi  = (bf16*)(base + OFF_S_HI);
    bf16* S_lo  = (bf16*)(base + OFF_S_LO);
    bf16* Wt_hi = (bf16*)(base + OFF_WT_HI);
    bf16* Wt_lo = (bf16*)(base + OFF_WT_LO);
    bf16* Hp_hi = (bf16*)(base + OFF_HP_HI);
    bf16* Hp_lo = (bf16*)(base + OFF_HP_LO);
    bf16* Hs_hi = (bf16*)(base + OFF_HS_HI);
    bf16* Hs_lo = (bf16*)(base + OFF_HS_LO);
    bf16* Vt_hi = (bf16*)(base + OFF_VT_HI);
    bf16* Vt_lo = (bf16*)(base + OFF_VT_LO);

    cudaFuncSetAttribute(gemm_kernel<0, 512, 512, 16, 512, false>,
                         cudaFuncAttributeMaxDynamicSharedMemorySize, SMEMSZ);
    cudaFuncSetAttribute(gemm_kernel<1, 512, 512, 16, CHUNK, false>,
                         cudaFuncAttributeMaxDynamicSharedMemorySize, SMEMSZ);
    cudaFuncSetAttribute(gemm_kernel<2, CHUNK, NR, CHUNK / 32, 512, false>,
                         cudaFuncAttributeMaxDynamicSharedMemorySize, SMEMSZ);
    cudaFuncSetAttribute(gemm_kernel<2, CHUNK, NR, CHUNK / 32, 512, true>,
                         cudaFuncAttributeMaxDynamicSharedMemorySize, SMEMSZ);

    convert_feats<<<dim3(NR * KD / 4 / 256, 2), 256>>>(feat_p, feat_s);
    transpose_w<<<dim3(16, 16), dim3(32, 32)>>>(weight);
    transpose_vs<<<dim3(16, 256), dim3(32, 32)>>>(feat_s);

    // proj: M=8192 N=512 K=512
    gemm_kernel<0, 512, 512, 16, 512, false><<<dim3(4, 64), 256, SMEMSZ>>>(
        Fp_hi, Fp_lo, Wt_hi, Wt_lo, Hp_hi, Hp_lo, nullptr, 0);
    gemm_kernel<0, 512, 512, 16, 512, false><<<dim3(4, 64), 256, SMEMSZ>>>(
        Fs_hi, Fs_lo, Wt_hi, Wt_lo, Hs_hi, Hs_lo, nullptr, 0);

    // chunked S + C accumulation
    for (int c = 0; c < NCHUNK; c++) {
        const int j0 = c * CHUNK;
        gemm_kernel<1, 512, 512, 16, CHUNK, false><<<dim3(CHUNK / 128, 64), 256, SMEMSZ>>>(
            Hp_hi, Hp_lo, Hs_hi + (size_t)j0 * 512, Hs_lo + (size_t)j0 * 512,
            S_hi, S_lo, nullptr, c * (CHUNK / 128) * 64);
        if (c == 0)
            gemm_kernel<2, CHUNK, NR, CHUNK / 32, 512, false><<<dim3(4, 64), 256, SMEMSZ>>>(
                S_hi, S_lo, Vt_hi + j0, Vt_lo + j0, nullptr, nullptr, out, 0);
        else
            gemm_kernel<2, CHUNK, NR, CHUNK / 32, 512, true><<<dim3(4, 64), 256, SMEMSZ>>>(
                S_hi, S_lo, Vt_hi + j0, Vt_lo + j0, nullptr, nullptr, out, 0);
    }

    reduce_kernel<<<1, 1024>>>();
    scale_kernel<<<(NR * KD) / (4 * 256), 256>>>(out);
}

// round 10
// speedup vs baseline: 1.0662x; 1.0662x over previous
#include <cuda_runtime.h>
#include <cuda_bf16.h>
#include <cstdint>

typedef __nv_bfloat16 bf16;

#define KD  512
#define NR  8192
#define CHUNK 1024
#define NCHUNK (NR / CHUNK)
#define NPART (NCHUNK * (CHUNK / 128) * 64)   // 4096

// stage (bytes): Ahi@0  Alo@10240  Bhi@20480  Blo@30720 ; stage = 40960 B
#define STAGE_BYTES 40960
#define STAGE_ELEMS 20480
#define NSTAGE 3
#define SMEMSZ (STAGE_BYTES * NSTAGE)   // 122880 B
#define MB (1024 * 1024)

// ---- single scratch buffer (81 MB total statics — proven safe) ----
#define OFF_FP_HI  (0 * MB)
#define OFF_FP_LO  (8 * MB)
#define OFF_FS_HI  (16 * MB)
#define OFF_FS_LO  (24 * MB)
#define OFF_S_HI   (0 * MB)
#define OFF_S_LO   (16 * MB)
#define OFF_WT_HI  (32 * MB)
#define OFF_WT_LO  (32 * MB + 512 * 1024)
#define OFF_HP_HI  (33 * MB)
#define OFF_HP_LO  (41 * MB)
#define OFF_HS_HI  (49 * MB)
#define OFF_HS_LO  (57 * MB)
#define OFF_VT_HI  (65 * MB)
#define OFF_VT_LO  (73 * MB)
#define BUF_BYTES  (81 * MB)

__device__ __align__(1024) char g_buf[BUF_BYTES];
__device__ float g_part[NPART];
__device__ float g_scale[1];

// ---------------- helpers ----------------
__device__ __forceinline__ void split_bf(float v, bf16& hi, bf16& lo)
{
    hi = __float2bfloat16(v);
    lo = __float2bfloat16(v - __bfloat162float(hi));
}
__device__ __forceinline__ uint32_t pack2(bf16 a, bf16 b)
{
    return (uint32_t)__bfloat16_as_ushort(a) | ((uint32_t)__bfloat16_as_ushort(b) << 16);
}
#define MMA_BF16(d, a0, a1, a2, a3, b0, b1)                                   \
    asm volatile(                                                             \
        "mma.sync.aligned.m16n8k16.row.col.f32.bf16.bf16.f32 "                \
        "{%0,%1,%2,%3},{%4,%5,%6,%7},{%8,%9},{%0,%1,%2,%3};"                  \
        : "+f"(d[0]), "+f"(d[1]), "+f"(d[2]), "+f"(d[3])                      \
        : "r"(a0), "r"(a1), "r"(a2), "r"(a3), "r"(b0), "r"(b1))

#define LDSM_X4(r0, r1, r2, r3, addr)                                         \
    asm volatile("ldmatrix.sync.aligned.m8n8.x4.shared.b16 {%0,%1,%2,%3}, [%4];" \
        : "=r"(r0), "=r"(r1), "=r"(r2), "=r"(r3) : "r"(addr))

#define CPA16(dst, src) \
    asm volatile("cp.async.cg.shared.global [%0], [%1], 16;" :: "r"(dst), "l"(src))

// ---------------- elementwise split of feats ----------------
__global__ __launch_bounds__(256) void convert_feats(const float* __restrict__ fp,
                                                     const float* __restrict__ fs)
{
    size_t i = (size_t)blockIdx.x * 256 + threadIdx.x;
    const float4 v = ((const float4*)(blockIdx.y ? fs : fp))[i];
    bf16* Hh = (bf16*)(g_buf + (blockIdx.y ? OFF_FS_HI : OFF_FP_HI));
    bf16* Hl = (bf16*)(g_buf + (blockIdx.y ? OFF_FS_LO : OFF_FP_LO));
    bf16 h0, l0, h1, l1, h2, l2, h3, l3;
    split_bf(v.x, h0, l0); split_bf(v.y, h1, l1);
    split_bf(v.z, h2, l2); split_bf(v.w, h3, l3);
    ((uint2*)Hh)[i] = make_uint2(pack2(h0, h1), pack2(h2, h3));
    ((uint2*)Hl)[i] = make_uint2(pack2(l0, l1), pack2(l2, l3));
}

// ---------------- transpose W (512x512) -> Wt hi/lo ----------------
__global__ void transpose_w(const float* __restrict__ W)
{
    __shared__ float s[32][33];
    int k = blockIdx.y * 32 + threadIdx.y;
    int n = blockIdx.x * 32 + threadIdx.x;
    s[threadIdx.y][threadIdx.x] = W[k * KD + n];
    __syncthreads();
    int nn = blockIdx.x * 32 + threadIdx.y;
    int kk = blockIdx.y * 32 + threadIdx.x;
    float v = s[threadIdx.x][threadIdx.y];
    bf16 h, l; split_bf(v, h, l);
    ((bf16*)(g_buf + OFF_WT_HI))[nn * KD + kk] = h;
    ((bf16*)(g_buf + OFF_WT_LO))[nn * KD + kk] = l;
}

// ---------------- transpose feat_s (8192x512) -> Vt hi/lo (512x8192) ----------
__global__ void transpose_vs(const float* __restrict__ fs)
{
    __shared__ float s[32][33];
    int k = blockIdx.y * 32 + threadIdx.y;
    int n = blockIdx.x * 32 + threadIdx.x;
    s[threadIdx.y][threadIdx.x] = fs[(size_t)k * KD + n];
    __syncthreads();
    int nn = blockIdx.x * 32 + threadIdx.y;
    int kk = blockIdx.y * 32 + threadIdx.x;
    float v = s[threadIdx.x][threadIdx.y];
    bf16 h, l; split_bf(v, h, l);
    ((bf16*)(g_buf + OFF_VT_HI))[(size_t)nn * NR + kk] = h;
    ((bf16*)(g_buf + OFF_VT_LO))[(size_t)nn * NR + kk] = l;
}

// ---------------- unified GEMM: D[128,128] tile = A[128,K] * B[128,K]^T ------
// bf16x3 (hi*hi + hi*lo + lo*hi). ldmatrix fragment loads, B loaded once.
// 3-stage cp.async; warp grid 2x4: warp tile 64x32.
extern __shared__ char s_raw[];

template <int MODE, int LDA, int LDB, int KTILES, int LDO, bool ACCUM>
__global__ __launch_bounds__(256, 1) void gemm_kernel(
    const bf16* __restrict__ Ahi, const bf16* __restrict__ Alo,
    const bf16* __restrict__ Bhi, const bf16* __restrict__ Blo,
    bf16* __restrict__ Ohi, bf16* __restrict__ Olo,
    float* __restrict__ Of, int part_off)
{
    bf16* smbase = (bf16*)s_raw;
    const int tid = threadIdx.x, lane = tid & 31, warp = tid >> 5;
    const int wm = (warp >> 2) * 64;
    const int wn = (warp & 3) * 32;
    const int m0 = blockIdx.y * 128, n0 = blockIdx.x * 128;

    // loader: 128 rows, 2 threads/row, 2x16B per thread per region (8 total)
    const int ra = tid >> 1, ca = (tid & 1) * 16;
    const bf16* pAh = Ahi + (size_t)(m0 + ra) * LDA + ca;
    const bf16* pAl = Alo + (size_t)(m0 + ra) * LDA + ca;
    const bf16* pBh = Bhi + (size_t)(n0 + ra) * LDB + ca;
    const bf16* pBl = Blo + (size_t)(n0 + ra) * LDB + ca;
    const uint32_t sbase = (uint32_t)__cvta_generic_to_shared(smbase);
    const uint32_t oAh = sbase + (uint32_t)(ra * 40 + ca) * 2;
    const uint32_t oAl = oAh + 10240;
    const uint32_t oBh = oAh + 20480;
    const uint32_t oBl = oAh + 30720;

    auto load_stage = [&](int st, int kt) {
        const uint32_t s = (uint32_t)st * STAGE_BYTES;
        const int ko = kt * 32;
        CPA16(oAh + s,      pAh + ko);
        CPA16(oAh + s + 16, pAh + ko + 8);
        CPA16(oAl + s,      pAl + ko);
        CPA16(oAl + s + 16, pAl + ko + 8);
        CPA16(oBh + s,      pBh + ko);
        CPA16(oBh + s + 16, pBh + ko + 8);
        CPA16(oBl + s,      pBl + ko);
        CPA16(oBl + s + 16, pBl + ko + 8);
    };

    // ldmatrix lane address components (bytes)
    const uint32_t laneA = (uint32_t)((wm + (lane & 15)) * 40 + ((lane >> 4) * 8)) * 2;
    const uint32_t laneB = (uint32_t)((wn + ((lane >> 4) * 8) + (lane & 7)) * 40
                                      + (((lane >> 3) & 1) * 8)) * 2 + 20480;

    float acc[4][4][4];
    #pragma unroll
    for (int a = 0; a < 4; a++)
        #pragma unroll
        for (int b = 0; b < 4; b++)
            #pragma unroll
            for (int c = 0; c < 4; c++) acc[a][b][c] = 0.f;

    load_stage(0, 0);
    asm volatile("cp.async.commit_group;");
    load_stage(1, 1);
    asm volatile("cp.async.commit_group;");

    int stage = 0;
    for (int kt = 0; kt < KTILES; kt++) {
        asm volatile("cp.async.wait_group 1;");
        __syncthreads();
        // slot (stage+2)%3 held kt-1 (consumed before the barrier above)
        if (kt + 2 < KTILES)
            load_stage((stage + 2) % NSTAGE, kt + 2);
        asm volatile("cp.async.commit_group;");

        const uint32_t sb = sbase + (uint32_t)stage * STAGE_BYTES;
        const uint32_t aA = sb + laneA;
        const uint32_t aB = sb + laneB;
        #pragma unroll
        for (int s = 0; s < 2; s++) {
            const uint32_t so = (uint32_t)s * 32;
            uint32_t bh[4][2], bl[4][2], af[4][4];

            // B fragments (hi and lo), two n-tiles per ldmatrix.x4
            LDSM_X4(bh[0][0], bh[0][1], bh[1][0], bh[1][1], aB + so);
            LDSM_X4(bh[2][0], bh[2][1], bh[3][0], bh[3][1], aB + so + 1280);
            LDSM_X4(bl[0][0], bl[0][1], bl[1][0], bl[1][1], aB + so + 10240);
            LDSM_X4(bl[2][0], bl[2][1], bl[3][0], bl[3][1], aB + so + 10240 + 1280);

            // pass 1: A_hi -> hi*hi + hi*lo
            #pragma unroll
            for (int mi = 0; mi < 4; mi++)
                LDSM_X4(af[mi][0], af[mi][1], af[mi][2], af[mi][3],
                        aA + so + (uint32_t)mi * 1280);
            #pragma unroll
            for (int ni = 0; ni < 4; ni++)
                #pragma unroll
                for (int mi = 0; mi < 4; mi++) {
                    MMA_BF16(acc[mi][ni], af[mi][0], af[mi][1], af[mi][2], af[mi][3],
                             bh[ni][0], bh[ni][1]);
                    MMA_BF16(acc[mi][ni], af[mi][0], af[mi][1], af[mi][2], af[mi][3],
                             bl[ni][0], bl[ni][1]);
                }

            // pass 2: A_lo -> lo*hi (reuse af regs)
            #pragma unroll
            for (int mi = 0; mi < 4; mi++)
                LDSM_X4(af[mi][0], af[mi][1], af[mi][2], af[mi][3],
                        aA + so + 10240 + (uint32_t)mi * 1280);
            #pragma unroll
            for (int ni = 0; ni < 4; ni++)
                #pragma unroll
                for (int mi = 0; mi < 4; mi++)
                    MMA_BF16(acc[mi][ni], af[mi][0], af[mi][1], af[mi][2], af[mi][3],
                             bh[ni][0], bh[ni][1]);
        }
        stage = (stage + 1 == NSTAGE) ? 0 : stage + 1;
    }

    // ---------------- epilogue ----------------
    float s2 = 0.f;
    #pragma unroll
    for (int mi = 0; mi < 4; mi++)
        #pragma unroll
        for (int ni = 0; ni < 4; ni++) {
            const int m = m0 + wm + mi * 16 + (lane >> 2);
            const int n = n0 + wn + ni * 8 + (lane & 3) * 2;
            float v0 = acc[mi][ni][0], v1 = acc[mi][ni][1];
            float v2 = acc[mi][ni][2], v3 = acc[mi][ni][3];
            if constexpr (MODE == 1) {
                v0 = fmaxf(v0, 0.f); v1 = fmaxf(v1, 0.f);
                v2 = fmaxf(v2, 0.f); v3 = fmaxf(v3, 0.f);
                s2 = fmaf(v0, v0, s2); s2 = fmaf(v1, v1, s2);
                s2 = fmaf(v2, v2, s2); s2 = fmaf(v3, v3, s2);
            }
            if constexpr (MODE == 2) {
                float2* p0 = (float2*)&Of[(size_t)m * LDO + n];
                float2* p1 = (float2*)&Of[(size_t)(m + 8) * LDO + n];
                if constexpr (ACCUM) {
                    float2 o0 = *p0, o1 = *p1;
                    *p0 = make_float2(o0.x + v0, o0.y + v1);
                    *p1 = make_float2(o1.x + v2, o1.y + v3);
                } else {
                    *p0 = make_float2(v0, v1);
                    *p1 = make_float2(v2, v3);
                }
            } else {
                bf16 h0, l0, h1, l1;
                split_bf(v0, h0, l0); split_bf(v1, h1, l1);
                *(uint32_t*)&Ohi[(size_t)m * LDO + n] = pack2(h0, h1);
                *(uint32_t*)&Olo[(size_t)m * LDO + n] = pack2(l0, l1);
                split_bf(v2, h0, l0); split_bf(v3, h1, l1);
                *(uint32_t*)&Ohi[(size_t)(m + 8) * LDO + n] = pack2(h0, h1);
                *(uint32_t*)&Olo[(size_t)(m + 8) * LDO + n] = pack2(l0, l1);
            }
        }

    if constexpr (MODE == 1) {
        __syncthreads();
        float* sf = (float*)s_raw;
        sf[tid] = s2;
        __syncthreads();
        #pragma unroll
        for (int off = 128; off > 0; off >>= 1) {
            if (tid < off) sf[tid] += sf[tid + off];
            __syncthreads();
        }
        if (tid == 0) g_part[part_off + blockIdx.y * gridDim.x + blockIdx.x] = sf[0];
    }
}

// ---------------- reduce NPART partials -> 1/fro -----------------------------
__global__ void reduce_kernel()
{
    __shared__ float rs[1024];
    int t = threadIdx.x;
    float v = 0.f;
    #pragma unroll
    for (int i = 0; i < NPART / 1024; i++) v += g_part[t + 1024 * i];
    rs[t] = v;
    __syncthreads();
    #pragma unroll
    for (int off = 512; off > 0; off >>= 1) {
        if (t < off) rs[t] += rs[t + off];
        __syncthreads();
    }
    if (t == 0) g_scale[0] = 1.0f / sqrtf(rs[0]);
}

// ---------------- scale output in place --------------------------------------
__global__ __launch_bounds__(256) void scale_kernel(float* __restrict__ out)
{
    const float s = g_scale[0];
    size_t i = (size_t)blockIdx.x * blockDim.x + threadIdx.x;
    float4* o = (float4*)out;
    float4 v = o[i];
    v.x *= s; v.y *= s; v.z *= s; v.w *= s;
    o[i] = v;
}

// ---------------- launch ----------------
extern "C" void kernel_launch(void* const* d_in, const int* in_sizes, int n_in,
                              void* d_out, int out_size)
{
    (void)in_sizes; (void)n_in; (void)out_size;
    const float* feat_p = (const float*)d_in[0];
    const float* feat_s = (const float*)d_in[1];
    const float* weight = (const float*)d_in[2];
    float* out = (float*)d_out;

    void* basep = nullptr;
    cudaGetSymbolAddress(&basep, g_buf);
    char* base = (char*)basep;
    bf16* Fp_hi = (bf16*)(base + OFF_FP_HI);
    bf16* Fp_lo = (bf16*)(base + OFF_FP_LO);
    bf16* Fs_hi = (bf16*)(base + OFF_FS_HI);
    bf16* Fs_lo = (bf16*)(base + OFF_FS_LO);
    bf16* S_hi  = (bf16*)(base + OFF_S_HI);
    bf16* S_lo  = (bf16*)(base + OFF_S_LO);
    bf16* Wt_hi = (bf16*)(base + OFF_WT_HI);
    bf16* Wt_lo = (bf16*)(base + OFF_WT_LO);
    bf16* Hp_hi = (bf16*)(base + OFF_HP_HI);
    bf16* Hp_lo = (bf16*)(base + OFF_HP_LO);
    bf16* Hs_hi = (bf16*)(base + OFF_HS_HI);
    bf16* Hs_lo = (bf16*)(base + OFF_HS_LO);
    bf16* Vt_hi = (bf16*)(base + OFF_VT_HI);
    bf16* Vt_lo = (bf16*)(base + OFF_VT_LO);

    cudaFuncSetAttribute(gemm_kernel<0, 512, 512, 16, 512, false>,
                         cudaFuncAttributeMaxDynamicSharedMemorySize, SMEMSZ);
    cudaFuncSetAttribute(gemm_kernel<1, 512, 512, 16, CHUNK, false>,
                         cudaFuncAttributeMaxDynamicSharedMemorySize, SMEMSZ);
    cudaFuncSetAttribute(gemm_kernel<2, CHUNK, NR, CHUNK / 32, 512, false>,
                         cudaFuncAttributeMaxDynamicSharedMemorySize, SMEMSZ);
    cudaFuncSetAttribute(gemm_kernel<2, CHUNK, NR, CHUNK / 32, 512, true>,
                         cudaFuncAttributeMaxDynamicSharedMemorySize, SMEMSZ);

    convert_feats<<<dim3(NR * KD / 4 / 256, 2), 256>>>(feat_p, feat_s);
    transpose_w<<<dim3(16, 16), dim3(32, 32)>>>(weight);
    transpose_vs<<<dim3(16, 256), dim3(32, 32)>>>(feat_s);

    // proj: M=8192 N=512 K=512
    gemm_kernel<0, 512, 512, 16, 512, false><<<dim3(4, 64), 256, SMEMSZ>>>(
        Fp_hi, Fp_lo, Wt_hi, Wt_lo, Hp_hi, Hp_lo, nullptr, 0);
    gemm_kernel<0, 512, 512, 16, 512, false><<<dim3(4, 64), 256, SMEMSZ>>>(
        Fs_hi, Fs_lo, Wt_hi, Wt_lo, Hs_hi, Hs_lo, nullptr, 0);

    // chunked S + C accumulation
    for (int c = 0; c < NCHUNK; c++) {
        const int j0 = c * CHUNK;
        gemm_kernel<1, 512, 512, 16, CHUNK, false><<<dim3(CHUNK / 128, 64), 256, SMEMSZ>>>(
            Hp_hi, Hp_lo, Hs_hi + (size_t)j0 * 512, Hs_lo + (size_t)j0 * 512,
            S_hi, S_lo, nullptr, c * (CHUNK / 128) * 64);
        if (c == 0)
            gemm_kernel<2, CHUNK, NR, CHUNK / 32, 512, false><<<dim3(4, 64), 256, SMEMSZ>>>(
                S_hi, S_lo, Vt_hi + j0, Vt_lo + j0, nullptr, nullptr, out, 0);
        else
            gemm_kernel<2, CHUNK, NR, CHUNK / 32, 512, true><<<dim3(4, 64), 256, SMEMSZ>>>(
                S_hi, S_lo, Vt_hi + j0, Vt_lo + j0, nullptr, nullptr, out, 0);
    }

    reduce_kernel<<<1, 1024>>>();
    scale_kernel<<<(NR * KD) / (4 * 256), 256>>>(out);
}

// round 11
// speedup vs baseline: 1.1367x; 1.0662x over previous
#include <cuda_runtime.h>
#include <cuda_bf16.h>
#include <cstdint>

typedef __nv_bfloat16 bf16;

#define KD  512
#define NR  8192
#define CHUNK 1024
#define NCHUNK (NR / CHUNK)
#define NPART (NCHUNK * (CHUNK / 128) * 64)   // 4096

// stage (bytes): Ahi@0  Alo@10240  Bhi@20480  Blo@30720 ; stage = 40960 B
#define STAGE_BYTES 40960
#define NSTAGE 3
#define SMEMSZ (STAGE_BYTES * NSTAGE)   // 122880 B
#define NTHREADS 512
#define MB (1024 * 1024)

// ---- single scratch buffer (81 MB total statics — proven safe) ----
#define OFF_FP_HI  (0 * MB)
#define OFF_FP_LO  (8 * MB)
#define OFF_FS_HI  (16 * MB)
#define OFF_FS_LO  (24 * MB)
#define OFF_S_HI   (0 * MB)
#define OFF_S_LO   (16 * MB)
#define OFF_WT_HI  (32 * MB)
#define OFF_WT_LO  (32 * MB + 512 * 1024)
#define OFF_HP_HI  (33 * MB)
#define OFF_HP_LO  (41 * MB)
#define OFF_HS_HI  (49 * MB)
#define OFF_HS_LO  (57 * MB)
#define OFF_VT_HI  (65 * MB)
#define OFF_VT_LO  (73 * MB)
#define BUF_BYTES  (81 * MB)

__device__ __align__(1024) char g_buf[BUF_BYTES];
__device__ float g_part[NPART];
__device__ float g_scale[1];

// ---------------- helpers ----------------
__device__ __forceinline__ void split_bf(float v, bf16& hi, bf16& lo)
{
    hi = __float2bfloat16(v);
    lo = __float2bfloat16(v - __bfloat162float(hi));
}
__device__ __forceinline__ uint32_t pack2(bf16 a, bf16 b)
{
    return (uint32_t)__bfloat16_as_ushort(a) | ((uint32_t)__bfloat16_as_ushort(b) << 16);
}
#define MMA_BF16(d, a0, a1, a2, a3, b0, b1)                                   \
    asm volatile(                                                             \
        "mma.sync.aligned.m16n8k16.row.col.f32.bf16.bf16.f32 "                \
        "{%0,%1,%2,%3},{%4,%5,%6,%7},{%8,%9},{%0,%1,%2,%3};"                  \
        : "+f"(d[0]), "+f"(d[1]), "+f"(d[2]), "+f"(d[3])                      \
        : "r"(a0), "r"(a1), "r"(a2), "r"(a3), "r"(b0), "r"(b1))

#define LDSM_X4(r0, r1, r2, r3, addr)                                         \
    asm volatile("ldmatrix.sync.aligned.m8n8.x4.shared.b16 {%0,%1,%2,%3}, [%4];" \
        : "=r"(r0), "=r"(r1), "=r"(r2), "=r"(r3) : "r"(addr))

#define CPA16(dst, src) \
    asm volatile("cp.async.cg.shared.global [%0], [%1], 16;" :: "r"(dst), "l"(src))

// ---------------- elementwise split of feats ----------------
__global__ __launch_bounds__(256) void convert_feats(const float* __restrict__ fp,
                                                     const float* __restrict__ fs)
{
    size_t i = (size_t)blockIdx.x * 256 + threadIdx.x;
    const float4 v = ((const float4*)(blockIdx.y ? fs : fp))[i];
    bf16* Hh = (bf16*)(g_buf + (blockIdx.y ? OFF_FS_HI : OFF_FP_HI));
    bf16* Hl = (bf16*)(g_buf + (blockIdx.y ? OFF_FS_LO : OFF_FP_LO));
    bf16 h0, l0, h1, l1, h2, l2, h3, l3;
    split_bf(v.x, h0, l0); split_bf(v.y, h1, l1);
    split_bf(v.z, h2, l2); split_bf(v.w, h3, l3);
    ((uint2*)Hh)[i] = make_uint2(pack2(h0, h1), pack2(h2, h3));
    ((uint2*)Hl)[i] = make_uint2(pack2(l0, l1), pack2(l2, l3));
}

// ---------------- transpose W (512x512) -> Wt hi/lo ----------------
__global__ void transpose_w(const float* __restrict__ W)
{
    __shared__ float s[32][33];
    int k = blockIdx.y * 32 + threadIdx.y;
    int n = blockIdx.x * 32 + threadIdx.x;
    s[threadIdx.y][threadIdx.x] = W[k * KD + n];
    __syncthreads();
    int nn = blockIdx.x * 32 + threadIdx.y;
    int kk = blockIdx.y * 32 + threadIdx.x;
    float v = s[threadIdx.x][threadIdx.y];
    bf16 h, l; split_bf(v, h, l);
    ((bf16*)(g_buf + OFF_WT_HI))[nn * KD + kk] = h;
    ((bf16*)(g_buf + OFF_WT_LO))[nn * KD + kk] = l;
}

// ---------------- transpose feat_s (8192x512) -> Vt hi/lo (512x8192) ----------
__global__ void transpose_vs(const float* __restrict__ fs)
{
    __shared__ float s[32][33];
    int k = blockIdx.y * 32 + threadIdx.y;
    int n = blockIdx.x * 32 + threadIdx.x;
    s[threadIdx.y][threadIdx.x] = fs[(size_t)k * KD + n];
    __syncthreads();
    int nn = blockIdx.x * 32 + threadIdx.y;
    int kk = blockIdx.y * 32 + threadIdx.x;
    float v = s[threadIdx.x][threadIdx.y];
    bf16 h, l; split_bf(v, h, l);
    ((bf16*)(g_buf + OFF_VT_HI))[(size_t)nn * NR + kk] = h;
    ((bf16*)(g_buf + OFF_VT_LO))[(size_t)nn * NR + kk] = l;
}

// ---------------- unified GEMM: D[128,128] tile = A[128,K] * B[128,K]^T ------
// bf16x3 (hi*hi + hi*lo + lo*hi). 512 threads, warp grid 4x4 (warp tile 32x32).
// ldmatrix fragment loads; 3-stage cp.async.
extern __shared__ char s_raw[];

template <int MODE, int LDA, int LDB, int KTILES, int LDO, bool ACCUM>
__global__ __launch_bounds__(NTHREADS, 1) void gemm_kernel(
    const bf16* __restrict__ Ahi, const bf16* __restrict__ Alo,
    const bf16* __restrict__ Bhi, const bf16* __restrict__ Blo,
    bf16* __restrict__ Ohi, bf16* __restrict__ Olo,
    float* __restrict__ Of, int part_off)
{
    bf16* smbase = (bf16*)s_raw;
    const int tid = threadIdx.x, lane = tid & 31, warp = tid >> 5;
    const int wm = (warp >> 2) * 32;    // 4 m-groups of 32
    const int wn = (warp & 3) * 32;     // 4 n-groups of 32
    const int m0 = blockIdx.y * 128, n0 = blockIdx.x * 128;

    // loader: 128 rows, 4 threads/row, 1x16B per thread per region (4 total)
    const int ra = tid >> 2, ca = (tid & 3) * 8;
    const bf16* pAh = Ahi + (size_t)(m0 + ra) * LDA + ca;
    const bf16* pAl = Alo + (size_t)(m0 + ra) * LDA + ca;
    const bf16* pBh = Bhi + (size_t)(n0 + ra) * LDB + ca;
    const bf16* pBl = Blo + (size_t)(n0 + ra) * LDB + ca;
    const uint32_t sbase = (uint32_t)__cvta_generic_to_shared(smbase);
    const uint32_t oAh = sbase + (uint32_t)(ra * 40 + ca) * 2;
    const uint32_t oAl = oAh + 10240;
    const uint32_t oBh = oAh + 20480;
    const uint32_t oBl = oAh + 30720;

    auto load_stage = [&](int st, int kt) {
        const uint32_t s = (uint32_t)st * STAGE_BYTES;
        const int ko = kt * 32;
        CPA16(oAh + s, pAh + ko);
        CPA16(oAl + s, pAl + ko);
        CPA16(oBh + s, pBh + ko);
        CPA16(oBl + s, pBl + ko);
    };

    // ldmatrix lane address components (bytes)
    const uint32_t laneA = (uint32_t)((wm + (lane & 15)) * 40 + ((lane >> 4) * 8)) * 2;
    const uint32_t laneB = (uint32_t)((wn + ((lane >> 4) * 8) + (lane & 7)) * 40
                                      + (((lane >> 3) & 1) * 8)) * 2 + 20480;

    float acc[2][4][4];
    #pragma unroll
    for (int a = 0; a < 2; a++)
        #pragma unroll
        for (int b = 0; b < 4; b++)
            #pragma unroll
            for (int c = 0; c < 4; c++) acc[a][b][c] = 0.f;

    load_stage(0, 0);
    asm volatile("cp.async.commit_group;");
    load_stage(1, 1);
    asm volatile("cp.async.commit_group;");

    int stage = 0;
    for (int kt = 0; kt < KTILES; kt++) {
        asm volatile("cp.async.wait_group 1;");
        __syncthreads();
        // slot (stage+2)%3 held kt-1 (consumed before the barrier above)
        if (kt + 2 < KTILES)
            load_stage((stage + 2) % NSTAGE, kt + 2);
        asm volatile("cp.async.commit_group;");

        const uint32_t sb = sbase + (uint32_t)stage * STAGE_BYTES;
        const uint32_t aA = sb + laneA;
        const uint32_t aB = sb + laneB;
        #pragma unroll
        for (int s = 0; s < 2; s++) {
            const uint32_t so = (uint32_t)s * 32;
            uint32_t bh[4][2], bl[4][2], af[2][4];

            // B fragments (hi and lo): two n-tiles per ldmatrix.x4, 4 n-tiles total
            LDSM_X4(bh[0][0], bh[0][1], bh[1][0], bh[1][1], aB + so);
            LDSM_X4(bh[2][0], bh[2][1], bh[3][0], bh[3][1], aB + so + 1280);
            LDSM_X4(bl[0][0], bl[0][1], bl[1][0], bl[1][1], aB + so + 10240);
            LDSM_X4(bl[2][0], bl[2][1], bl[3][0], bl[3][1], aB + so + 10240 + 1280);

            // pass 1: A_hi -> hi*hi + hi*lo
            #pragma unroll
            for (int mi = 0; mi < 2; mi++)
                LDSM_X4(af[mi][0], af[mi][1], af[mi][2], af[mi][3],
                        aA + so + (uint32_t)mi * 1280);
            #pragma unroll
            for (int ni = 0; ni < 4; ni++)
                #pragma unroll
                for (int mi = 0; mi < 2; mi++) {
                    MMA_BF16(acc[mi][ni], af[mi][0], af[mi][1], af[mi][2], af[mi][3],
                             bh[ni][0], bh[ni][1]);
                    MMA_BF16(acc[mi][ni], af[mi][0], af[mi][1], af[mi][2], af[mi][3],
                             bl[ni][0], bl[ni][1]);
                }

            // pass 2: A_lo -> lo*hi (reuse af regs)
            #pragma unroll
            for (int mi = 0; mi < 2; mi++)
                LDSM_X4(af[mi][0], af[mi][1], af[mi][2], af[mi][3],
                        aA + so + 10240 + (uint32_t)mi * 1280);
            #pragma unroll
            for (int ni = 0; ni < 4; ni++)
                #pragma unroll
                for (int mi = 0; mi < 2; mi++)
                    MMA_BF16(acc[mi][ni], af[mi][0], af[mi][1], af[mi][2], af[mi][3],
                             bh[ni][0], bh[ni][1]);
        }
        stage = (stage + 1 == NSTAGE) ? 0 : stage + 1;
    }

    // ---------------- epilogue ----------------
    float s2 = 0.f;
    #pragma unroll
    for (int mi = 0; mi < 2; mi++)
        #pragma unroll
        for (int ni = 0; ni < 4; ni++) {
            const int m = m0 + wm + mi * 16 + (lane >> 2);
            const int n = n0 + wn + ni * 8 + (lane & 3) * 2;
            float v0 = acc[mi][ni][0], v1 = acc[mi][ni][1];
            float v2 = acc[mi][ni][2], v3 = acc[mi][ni][3];
            if constexpr (MODE == 1) {
                v0 = fmaxf(v0, 0.f); v1 = fmaxf(v1, 0.f);
                v2 = fmaxf(v2, 0.f); v3 = fmaxf(v3, 0.f);
                s2 = fmaf(v0, v0, s2); s2 = fmaf(v1, v1, s2);
                s2 = fmaf(v2, v2, s2); s2 = fmaf(v3, v3, s2);
            }
            if constexpr (MODE == 2) {
                float2* p0 = (float2*)&Of[(size_t)m * LDO + n];
                float2* p1 = (float2*)&Of[(size_t)(m + 8) * LDO + n];
                if constexpr (ACCUM) {
                    float2 o0 = *p0, o1 = *p1;
                    *p0 = make_float2(o0.x + v0, o0.y + v1);
                    *p1 = make_float2(o1.x + v2, o1.y + v3);
                } else {
                    *p0 = make_float2(v0, v1);
                    *p1 = make_float2(v2, v3);
                }
            } else {
                bf16 h0, l0, h1, l1;
                split_bf(v0, h0, l0); split_bf(v1, h1, l1);
                *(uint32_t*)&Ohi[(size_t)m * LDO + n] = pack2(h0, h1);
                *(uint32_t*)&Olo[(size_t)m * LDO + n] = pack2(l0, l1);
                split_bf(v2, h0, l0); split_bf(v3, h1, l1);
                *(uint32_t*)&Ohi[(size_t)(m + 8) * LDO + n] = pack2(h0, h1);
                *(uint32_t*)&Olo[(size_t)(m + 8) * LDO + n] = pack2(l0, l1);
            }
        }

    if constexpr (MODE == 1) {
        __syncthreads();
        float* sf = (float*)s_raw;
        sf[tid] = s2;
        __syncthreads();
        #pragma unroll
        for (int off = 256; off > 0; off >>= 1) {
            if (tid < off) sf[tid] += sf[tid + off];
            __syncthreads();
        }
        if (tid == 0) g_part[part_off + blockIdx.y * gridDim.x + blockIdx.x] = sf[0];
    }
}

// ---------------- reduce NPART partials -> 1/fro -----------------------------
__global__ void reduce_kernel()
{
    __shared__ float rs[1024];
    int t = threadIdx.x;
    float v = 0.f;
    #pragma unroll
    for (int i = 0; i < NPART / 1024; i++) v += g_part[t + 1024 * i];
    rs[t] = v;
    __syncthreads();
    #pragma unroll
    for (int off = 512; off > 0; off >>= 1) {
        if (t < off) rs[t] += rs[t + off];
        __syncthreads();
    }
    if (t == 0) g_scale[0] = 1.0f / sqrtf(rs[0]);
}

// ---------------- scale output in place --------------------------------------
__global__ __launch_bounds__(256) void scale_kernel(float* __restrict__ out)
{
    const float s = g_scale[0];
    size_t i = (size_t)blockIdx.x * blockDim.x + threadIdx.x;
    float4* o = (float4*)out;
    float4 v = o[i];
    v.x *= s; v.y *= s; v.z *= s; v.w *= s;
    o[i] = v;
}

// ---------------- launch ----------------
extern "C" void kernel_launch(void* const* d_in, const int* in_sizes, int n_in,
                              void* d_out, int out_size)
{
    (void)in_sizes; (void)n_in; (void)out_size;
    const float* feat_p = (const float*)d_in[0];
    const float* feat_s = (const float*)d_in[1];
    const float* weight = (const float*)d_in[2];
    float* out = (float*)d_out;

    void* basep = nullptr;
    cudaGetSymbolAddress(&basep, g_buf);
    char* base = (char*)basep;
    bf16* Fp_hi = (bf16*)(base + OFF_FP_HI);
    bf16* Fp_lo = (bf16*)(base + OFF_FP_LO);
    bf16* Fs_hi = (bf16*)(base + OFF_FS_HI);
    bf16* Fs_lo = (bf16*)(base + OFF_FS_LO);
    bf16* S_hi  = (bf16*)(base + OFF_S_HI);
    bf16* S_lo  = (bf16*)(base + OFF_S_LO);
    bf16* Wt_hi = (bf16*)(base + OFF_WT_HI);
    bf16* Wt_lo = (bf16*)(base + OFF_WT_LO);
    bf16* Hp_hi = (bf16*)(base + OFF_HP_HI);
    bf16* Hp_lo = (bf16*)(base + OFF_HP_LO);
    bf16* Hs_hi = (bf16*)(base + OFF_HS_HI);
    bf16* Hs_lo = (bf16*)(base + OFF_HS_LO);
    bf16* Vt_hi = (bf16*)(base + OFF_VT_HI);
    bf16* Vt_lo = (bf16*)(base + OFF_VT_LO);

    cudaFuncSetAttribute(gemm_kernel<0, 512, 512, 16, 512, false>,
                         cudaFuncAttributeMaxDynamicSharedMemorySize, SMEMSZ);
    cudaFuncSetAttribute(gemm_kernel<1, 512, 512, 16, CHUNK, false>,
                         cudaFuncAttributeMaxDynamicSharedMemorySize, SMEMSZ);
    cudaFuncSetAttribute(gemm_kernel<2, CHUNK, NR, CHUNK / 32, 512, false>,
                         cudaFuncAttributeMaxDynamicSharedMemorySize, SMEMSZ);
    cudaFuncSetAttribute(gemm_kernel<2, CHUNK, NR, CHUNK / 32, 512, true>,
                         cudaFuncAttributeMaxDynamicSharedMemorySize, SMEMSZ);

    convert_feats<<<dim3(NR * KD / 4 / 256, 2), 256>>>(feat_p, feat_s);
    transpose_w<<<dim3(16, 16), dim3(32, 32)>>>(weight);
    transpose_vs<<<dim3(16, 256), dim3(32, 32)>>>(feat_s);

    // proj: M=8192 N=512 K=512
    gemm_kernel<0, 512, 512, 16, 512, false><<<dim3(4, 64), NTHREADS, SMEMSZ>>>(
        Fp_hi, Fp_lo, Wt_hi, Wt_lo, Hp_hi, Hp_lo, nullptr, 0);
    gemm_kernel<0, 512, 512, 16, 512, false><<<dim3(4, 64), NTHREADS, SMEMSZ>>>(
        Fs_hi, Fs_lo, Wt_hi, Wt_lo, Hs_hi, Hs_lo, nullptr, 0);

    // chunked S + C accumulation
    for (int c = 0; c < NCHUNK; c++) {
        const int j0 = c * CHUNK;
        gemm_kernel<1, 512, 512, 16, CHUNK, false><<<dim3(CHUNK / 128, 64), NTHREADS, SMEMSZ>>>(
            Hp_hi, Hp_lo, Hs_hi + (size_t)j0 * 512, Hs_lo + (size_t)j0 * 512,
            S_hi, S_lo, nullptr, c * (CHUNK / 128) * 64);
        if (c == 0)
            gemm_kernel<2, CHUNK, NR, CHUNK / 32, 512, false><<<dim3(4, 64), NTHREADS, SMEMSZ>>>(
                S_hi, S_lo, Vt_hi + j0, Vt_lo + j0, nullptr, nullptr, out, 0);
        else
            gemm_kernel<2, CHUNK, NR, CHUNK / 32, 512, true><<<dim3(4, 64), NTHREADS, SMEMSZ>>>(
                S_hi, S_lo, Vt_hi + j0, Vt_lo + j0, nullptr, nullptr, out, 0);
    }

    reduce_kernel<<<1, 1024>>>();
    scale_kernel<<<(NR * KD) / (4 * 256), 256>>>(out);
}

// round 13
// speedup vs baseline: 1.7695x; 1.5566x over previous
#include <cuda_runtime.h>
#include <cuda_fp16.h>
#include <cstdint>

typedef __half fp16;

#define KD  512
#define NR  8192
#define CHUNK 1024
#define NCHUNK (NR / CHUNK)
#define NPART (NCHUNK * (CHUNK / 128) * 64)   // 4096

// stage (bytes): Ahi@0  Alo@10240  Bhi@20480  Blo@30720 ; stage = 40960 B
#define STAGE_BYTES 40960
#define NSTAGE 3
#define SMEMSZ (STAGE_BYTES * NSTAGE)   // 122880 B
#define NTHREADS 512
#define MB (1024 * 1024)

// ---- single scratch buffer (81 MB total statics — proven safe) ----
#define OFF_FP_HI  (0 * MB)
#define OFF_FP_LO  (8 * MB)
#define OFF_FS_HI  (16 * MB)
#define OFF_FS_LO  (24 * MB)
#define OFF_S_HI   (0 * MB)
#define OFF_S_LO   (16 * MB)   // unused now, kept in layout
#define OFF_WT_HI  (32 * MB)
#define OFF_WT_LO  (32 * MB + 512 * 1024)
#define OFF_HP_HI  (33 * MB)
#define OFF_HP_LO  (41 * MB)
#define OFF_HS_HI  (49 * MB)
#define OFF_HS_LO  (57 * MB)
#define OFF_VT_HI  (65 * MB)
#define OFF_VT_LO  (73 * MB)
#define BUF_BYTES  (81 * MB)

__device__ __align__(1024) char g_buf[BUF_BYTES];
__device__ float g_part[NPART];
__device__ float g_scale[1];

// ---------------- helpers ----------------
__device__ __forceinline__ void split_fp(float v, fp16& hi, fp16& lo)
{
    hi = __float2half(v);
    lo = __float2half(v - __half2float(hi));
}
__device__ __forceinline__ uint32_t pack2(fp16 a, fp16 b)
{
    return (uint32_t)__half_as_ushort(a) | ((uint32_t)__half_as_ushort(b) << 16);
}
#define MMA_F16(d, a0, a1, a2, a3, b0, b1)                                    \
    asm volatile(                                                             \
        "mma.sync.aligned.m16n8k16.row.col.f32.f16.f16.f32 "                  \
        "{%0,%1,%2,%3},{%4,%5,%6,%7},{%8,%9},{%0,%1,%2,%3};"                  \
        : "+f"(d[0]), "+f"(d[1]), "+f"(d[2]), "+f"(d[3])                      \
        : "r"(a0), "r"(a1), "r"(a2), "r"(a3), "r"(b0), "r"(b1))

#define LDSM_X4(r0, r1, r2, r3, addr)                                         \
    asm volatile("ldmatrix.sync.aligned.m8n8.x4.shared.b16 {%0,%1,%2,%3}, [%4];" \
        : "=r"(r0), "=r"(r1), "=r"(r2), "=r"(r3) : "r"(addr))

#define CPA16(dst, src) \
    asm volatile("cp.async.cg.shared.global [%0], [%1], 16;" :: "r"(dst), "l"(src))

// ---------------- elementwise split of feats ----------------
__global__ __launch_bounds__(256) void convert_feats(const float* __restrict__ fp,
                                                     const float* __restrict__ fs)
{
    size_t i = (size_t)blockIdx.x * 256 + threadIdx.x;
    const float4 v = ((const float4*)(blockIdx.y ? fs : fp))[i];
    fp16* Hh = (fp16*)(g_buf + (blockIdx.y ? OFF_FS_HI : OFF_FP_HI));
    fp16* Hl = (fp16*)(g_buf + (blockIdx.y ? OFF_FS_LO : OFF_FP_LO));
    fp16 h0, l0, h1, l1, h2, l2, h3, l3;
    split_fp(v.x, h0, l0); split_fp(v.y, h1, l1);
    split_fp(v.z, h2, l2); split_fp(v.w, h3, l3);
    ((uint2*)Hh)[i] = make_uint2(pack2(h0, h1), pack2(h2, h3));
    ((uint2*)Hl)[i] = make_uint2(pack2(l0, l1), pack2(l2, l3));
}

// ---------------- transpose W (512x512) -> Wt hi/lo ----------------
__global__ void transpose_w(const float* __restrict__ W)
{
    __shared__ float s[32][33];
    int k = blockIdx.y * 32 + threadIdx.y;
    int n = blockIdx.x * 32 + threadIdx.x;
    s[threadIdx.y][threadIdx.x] = W[k * KD + n];
    __syncthreads();
    int nn = blockIdx.x * 32 + threadIdx.y;
    int kk = blockIdx.y * 32 + threadIdx.x;
    float v = s[threadIdx.x][threadIdx.y];
    fp16 h, l; split_fp(v, h, l);
    ((fp16*)(g_buf + OFF_WT_HI))[nn * KD + kk] = h;
    ((fp16*)(g_buf + OFF_WT_LO))[nn * KD + kk] = l;
}

// ---------------- transpose feat_s (8192x512) -> Vt hi/lo (512x8192) ----------
__global__ void transpose_vs(const float* __restrict__ fs)
{
    __shared__ float s[32][33];
    int k = blockIdx.y * 32 + threadIdx.y;
    int n = blockIdx.x * 32 + threadIdx.x;
    s[threadIdx.y][threadIdx.x] = fs[(size_t)k * KD + n];
    __syncthreads();
    int nn = blockIdx.x * 32 + threadIdx.y;
    int kk = blockIdx.y * 32 + threadIdx.x;
    float v = s[threadIdx.x][threadIdx.y];
    fp16 h, l; split_fp(v, h, l);
    ((fp16*)(g_buf + OFF_VT_HI))[(size_t)nn * NR + kk] = h;
    ((fp16*)(g_buf + OFF_VT_LO))[(size_t)nn * NR + kk] = l;
}

// ---------------- unified GEMM: D[128,128] tile = A[128,K] * B[128,K]^T ------
// fp16 split. NPROD=2: A_hi*(B_hi + B_lo)  (drop A_lo term, err ~2^-12)
//             NPROD=3: + A_lo*B_hi        (err ~2^-24, for proj)
// 512 threads, warp grid 4x4 (warp tile 32x32); ldmatrix; 3-stage cp.async.
extern __shared__ char s_raw[];

template <int MODE, int NPROD, int LDA, int LDB, int KTILES, int LDO, bool ACCUM>
__global__ __launch_bounds__(NTHREADS, 1) void gemm_kernel(
    const fp16* __restrict__ Ahi, const fp16* __restrict__ Alo,
    const fp16* __restrict__ Bhi, const fp16* __restrict__ Blo,
    fp16* __restrict__ Ohi, fp16* __restrict__ Olo,
    float* __restrict__ Of, int part_off)
{
    fp16* smbase = (fp16*)s_raw;
    const int tid = threadIdx.x, lane = tid & 31, warp = tid >> 5;
    const int wm = (warp >> 2) * 32;
    const int wn = (warp & 3) * 32;
    const int m0 = blockIdx.y * 128, n0 = blockIdx.x * 128;

    // loader: 128 rows, 4 threads/row, 1x16B per thread per region
    const int ra = tid >> 2, ca = (tid & 3) * 8;
    const fp16* pAh = Ahi + (size_t)(m0 + ra) * LDA + ca;
    const fp16* pAl = Alo + (size_t)(m0 + ra) * LDA + ca;
    const fp16* pBh = Bhi + (size_t)(n0 + ra) * LDB + ca;
    const fp16* pBl = Blo + (size_t)(n0 + ra) * LDB + ca;
    const uint32_t sbase = (uint32_t)__cvta_generic_to_shared(smbase);
    const uint32_t oAh = sbase + (uint32_t)(ra * 40 + ca) * 2;
    const uint32_t oAl = oAh + 10240;
    const uint32_t oBh = oAh + 20480;
    const uint32_t oBl = oAh + 30720;

    auto load_stage = [&](int st, int kt) {
        const uint32_t s = (uint32_t)st * STAGE_BYTES;
        const int ko = kt * 32;
        CPA16(oAh + s, pAh + ko);
        if (NPROD == 3) CPA16(oAl + s, pAl + ko);
        CPA16(oBh + s, pBh + ko);
        CPA16(oBl + s, pBl + ko);
    };

    // ldmatrix lane address components (bytes)
    const uint32_t laneA = (uint32_t)((wm + (lane & 15)) * 40 + ((lane >> 4) * 8)) * 2;
    const uint32_t laneB = (uint32_t)((wn + ((lane >> 4) * 8) + (lane & 7)) * 40
                                      + (((lane >> 3) & 1) * 8)) * 2 + 20480;

    float acc[2][4][4];
    #pragma unroll
    for (int a = 0; a < 2; a++)
        #pragma unroll
        for (int b = 0; b < 4; b++)
            #pragma unroll
            for (int c = 0; c < 4; c++) acc[a][b][c] = 0.f;

    load_stage(0, 0);
    asm volatile("cp.async.commit_group;");
    load_stage(1, 1);
    asm volatile("cp.async.commit_group;");

    int stage = 0;
    for (int kt = 0; kt < KTILES; kt++) {
        asm volatile("cp.async.wait_group 1;");
        __syncthreads();
        if (kt + 2 < KTILES)
            load_stage((stage + 2) % NSTAGE, kt + 2);
        asm volatile("cp.async.commit_group;");

        const uint32_t sb = sbase + (uint32_t)stage * STAGE_BYTES;
        const uint32_t aA = sb + laneA;
        const uint32_t aB = sb + laneB;
        #pragma unroll
        for (int s = 0; s < 2; s++) {
            const uint32_t so = (uint32_t)s * 32;
            uint32_t bh[4][2], bl[4][2], af[2][4];

            LDSM_X4(bh[0][0], bh[0][1], bh[1][0], bh[1][1], aB + so);
            LDSM_X4(bh[2][0], bh[2][1], bh[3][0], bh[3][1], aB + so + 1280);
            LDSM_X4(bl[0][0], bl[0][1], bl[1][0], bl[1][1], aB + so + 10240);
            LDSM_X4(bl[2][0], bl[2][1], bl[3][0], bl[3][1], aB + so + 10240 + 1280);

            // A_hi: hi*hi + hi*lo
            #pragma unroll
            for (int mi = 0; mi < 2; mi++)
                LDSM_X4(af[mi][0], af[mi][1], af[mi][2], af[mi][3],
                        aA + so + (uint32_t)mi * 1280);
            #pragma unroll
            for (int ni = 0; ni < 4; ni++)
                #pragma unroll
                for (int mi = 0; mi < 2; mi++) {
                    MMA_F16(acc[mi][ni], af[mi][0], af[mi][1], af[mi][2], af[mi][3],
                            bh[ni][0], bh[ni][1]);
                    MMA_F16(acc[mi][ni], af[mi][0], af[mi][1], af[mi][2], af[mi][3],
                            bl[ni][0], bl[ni][1]);
                }

            if (NPROD == 3) {
                // A_lo * B_hi (proj only)
                #pragma unroll
                for (int mi = 0; mi < 2; mi++)
                    LDSM_X4(af[mi][0], af[mi][1], af[mi][2], af[mi][3],
                            aA + so + 10240 + (uint32_t)mi * 1280);
                #pragma unroll
                for (int ni = 0; ni < 4; ni++)
                    #pragma unroll
                    for (int mi = 0; mi < 2; mi++)
                        MMA_F16(acc[mi][ni], af[mi][0], af[mi][1], af[mi][2], af[mi][3],
                                bh[ni][0], bh[ni][1]);
            }
        }
        stage = (stage + 1 == NSTAGE) ? 0 : stage + 1;
    }

    // ---------------- epilogue ----------------
    float s2 = 0.f;
    #pragma unroll
    for (int mi = 0; mi < 2; mi++)
        #pragma unroll
        for (int ni = 0; ni < 4; ni++) {
            const int m = m0 + wm + mi * 16 + (lane >> 2);
            const int n = n0 + wn + ni * 8 + (lane & 3) * 2;
            float v0 = acc[mi][ni][0], v1 = acc[mi][ni][1];
            float v2 = acc[mi][ni][2], v3 = acc[mi][ni][3];
            if constexpr (MODE == 1) {
                // relu + sumsq + store S_hi only (S_lo never consumed)
                v0 = fmaxf(v0, 0.f); v1 = fmaxf(v1, 0.f);
                v2 = fmaxf(v2, 0.f); v3 = fmaxf(v3, 0.f);
                s2 = fmaf(v0, v0, s2); s2 = fmaf(v1, v1, s2);
                s2 = fmaf(v2, v2, s2); s2 = fmaf(v3, v3, s2);
                *(uint32_t*)&Ohi[(size_t)m * LDO + n] =
                    pack2(__float2half(v0), __float2half(v1));
                *(uint32_t*)&Ohi[(size_t)(m + 8) * LDO + n] =
                    pack2(__float2half(v2), __float2half(v3));
            } else if constexpr (MODE == 2) {
                float2* p0 = (float2*)&Of[(size_t)m * LDO + n];
                float2* p1 = (float2*)&Of[(size_t)(m + 8) * LDO + n];
                if constexpr (ACCUM) {
                    float2 o0 = *p0, o1 = *p1;
                    *p0 = make_float2(o0.x + v0, o0.y + v1);
                    *p1 = make_float2(o1.x + v2, o1.y + v3);
                } else {
                    *p0 = make_float2(v0, v1);
                    *p1 = make_float2(v2, v3);
                }
            } else {
                fp16 h0, l0, h1, l1;
                split_fp(v0, h0, l0); split_fp(v1, h1, l1);
                *(uint32_t*)&Ohi[(size_t)m * LDO + n] = pack2(h0, h1);
                *(uint32_t*)&Olo[(size_t)m * LDO + n] = pack2(l0, l1);
                split_fp(v2, h0, l0); split_fp(v3, h1, l1);
                *(uint32_t*)&Ohi[(size_t)(m + 8) * LDO + n] = pack2(h0, h1);
                *(uint32_t*)&Olo[(size_t)(m + 8) * LDO + n] = pack2(l0, l1);
            }
        }

    if constexpr (MODE == 1) {
        __syncthreads();
        float* sf = (float*)s_raw;
        sf[tid] = s2;
        __syncthreads();
        #pragma unroll
        for (int off = 256; off > 0; off >>= 1) {
            if (tid < off) sf[tid] += sf[tid + off];
            __syncthreads();
        }
        if (tid == 0) g_part[part_off + blockIdx.y * gridDim.x + blockIdx.x] = sf[0];
    }
}

// ---------------- reduce NPART partials -> 1/fro -----------------------------
__global__ void reduce_kernel()
{
    __shared__ float rs[1024];
    int t = threadIdx.x;
    float v = 0.f;
    #pragma unroll
    for (int i = 0; i < NPART / 1024; i++) v += g_part[t + 1024 * i];
    rs[t] = v;
    __syncthreads();
    #pragma unroll
    for (int off = 512; off > 0; off >>= 1) {
        if (t < off) rs[t] += rs[t + off];
        __syncthreads();
    }
    if (t == 0) g_scale[0] = 1.0f / sqrtf(rs[0]);
}

// ---------------- scale output in place --------------------------------------
__global__ __launch_bounds__(256) void scale_kernel(float* __restrict__ out)
{
    const float s = g_scale[0];
    size_t i = (size_t)blockIdx.x * blockDim.x + threadIdx.x;
    float4* o = (float4*)out;
    float4 v = o[i];
    v.x *= s; v.y *= s; v.z *= s; v.w *= s;
    o[i] = v;
}

// ---------------- launch ----------------
extern "C" void kernel_launch(void* const* d_in, const int* in_sizes, int n_in,
                              void* d_out, int out_size)
{
    (void)in_sizes; (void)n_in; (void)out_size;
    const float* feat_p = (const float*)d_in[0];
    const float* feat_s = (const float*)d_in[1];
    const float* weight = (const float*)d_in[2];
    float* out = (float*)d_out;

    void* basep = nullptr;
    cudaGetSymbolAddress(&basep, g_buf);
    char* base = (char*)basep;
    fp16* Fp_hi = (fp16*)(base + OFF_FP_HI);
    fp16* Fp_lo = (fp16*)(base + OFF_FP_LO);
    fp16* Fs_hi = (fp16*)(base + OFF_FS_HI);
    fp16* Fs_lo = (fp16*)(base + OFF_FS_LO);
    fp16* S_hi  = (fp16*)(base + OFF_S_HI);
    fp16* Wt_hi = (fp16*)(base + OFF_WT_HI);
    fp16* Wt_lo = (fp16*)(base + OFF_WT_LO);
    fp16* Hp_hi = (fp16*)(base + OFF_HP_HI);
    fp16* Hp_lo = (fp16*)(base + OFF_HP_LO);
    fp16* Hs_hi = (fp16*)(base + OFF_HS_HI);
    fp16* Hs_lo = (fp16*)(base + OFF_HS_LO);
    fp16* Vt_hi = (fp16*)(base + OFF_VT_HI);
    fp16* Vt_lo = (fp16*)(base + OFF_VT_LO);

    cudaFuncSetAttribute(gemm_kernel<0, 3, 512, 512, 16, 512, false>,
                         cudaFuncAttributeMaxDynamicSharedMemorySize, SMEMSZ);
    cudaFuncSetAttribute(gemm_kernel<1, 2, 512, 512, 16, CHUNK, false>,
                         cudaFuncAttributeMaxDynamicSharedMemorySize, SMEMSZ);
    cudaFuncSetAttribute(gemm_kernel<2, 2, CHUNK, NR, CHUNK / 32, 512, false>,
                         cudaFuncAttributeMaxDynamicSharedMemorySize, SMEMSZ);
    cudaFuncSetAttribute(gemm_kernel<2, 2, CHUNK, NR, CHUNK / 32, 512, true>,
                         cudaFuncAttributeMaxDynamicSharedMemorySize, SMEMSZ);

    convert_feats<<<dim3(NR * KD / 4 / 256, 2), 256>>>(feat_p, feat_s);
    transpose_w<<<dim3(16, 16), dim3(32, 32)>>>(weight);
    transpose_vs<<<dim3(16, 256), dim3(32, 32)>>>(feat_s);

    // proj (3-term, near-exact): M=8192 N=512 K=512
    gemm_kernel<0, 3, 512, 512, 16, 512, false><<<dim3(4, 64), NTHREADS, SMEMSZ>>>(
        Fp_hi, Fp_lo, Wt_hi, Wt_lo, Hp_hi, Hp_lo, nullptr, 0);
    gemm_kernel<0, 3, 512, 512, 16, 512, false><<<dim3(4, 64), NTHREADS, SMEMSZ>>>(
        Fs_hi, Fs_lo, Wt_hi, Wt_lo, Hs_hi, Hs_lo, nullptr, 0);

    // chunked S + C accumulation (2-term fp16)
    for (int c = 0; c < NCHUNK; c++) {
        const int j0 = c * CHUNK;
        gemm_kernel<1, 2, 512, 512, 16, CHUNK, false><<<dim3(CHUNK / 128, 64), NTHREADS, SMEMSZ>>>(
            Hp_hi, Hp_lo, Hs_hi + (size_t)j0 * 512, Hs_lo + (size_t)j0 * 512,
            S_hi, nullptr, nullptr, c * (CHUNK / 128) * 64);
        if (c == 0)
            gemm_kernel<2, 2, CHUNK, NR, CHUNK / 32, 512, false><<<dim3(4, 64), NTHREADS, SMEMSZ>>>(
                S_hi, nullptr, Vt_hi + j0, Vt_lo + j0, nullptr, nullptr, out, 0);
        else
            gemm_kernel<2, 2, CHUNK, NR, CHUNK / 32, 512, true><<<dim3(4, 64), NTHREADS, SMEMSZ>>>(
                S_hi, nullptr, Vt_hi + j0, Vt_lo + j0, nullptr, nullptr, out, 0);
    }

    reduce_kernel<<<1, 1024>>>();
    scale_kernel<<<(NR * KD) / (4 * 256), 256>>>(out);
}

// round 14
// speedup vs baseline: 2.6470x; 1.4959x over previous
#include <cuda_runtime.h>
#include <cuda_fp16.h>
#include <cstdint>

typedef __half fp16;

#define KD  512
#define NR  8192
#define CHUNK 1024
#define NCHUNK (NR / CHUNK)
#define NPART (NCHUNK * (CHUNK / 128) * 64)   // 4096

// stage (bytes): Ahi@0  Alo@10240  Bhi@20480  Blo@30720 ; stage = 40960 B
#define STAGE_BYTES 40960
#define NSTAGE 3
#define SMEMSZ (STAGE_BYTES * NSTAGE)   // 122880 B
#define NTHREADS 512
#define MB (1024 * 1024)

// ---- single scratch buffer (81 MB total statics — proven safe) ----
#define OFF_FP_HI  (0 * MB)
#define OFF_FP_LO  (8 * MB)
#define OFF_FS_HI  (16 * MB)
#define OFF_FS_LO  (24 * MB)
#define OFF_S_HI   (0 * MB)
#define OFF_WT_HI  (32 * MB)
#define OFF_WT_LO  (32 * MB + 512 * 1024)
#define OFF_HP_HI  (33 * MB)
#define OFF_HP_LO  (41 * MB)
#define OFF_HS_HI  (49 * MB)
#define OFF_HS_LO  (57 * MB)
#define OFF_VT_HI  (65 * MB)
#define OFF_VT_LO  (73 * MB)
#define BUF_BYTES  (81 * MB)

__device__ __align__(1024) char g_buf[BUF_BYTES];
__device__ float g_part[NPART];
__device__ float g_scale[1];

// ---------------- helpers ----------------
__device__ __forceinline__ void split_fp(float v, fp16& hi, fp16& lo)
{
    hi = __float2half(v);
    lo = __float2half(v - __half2float(hi));
}
__device__ __forceinline__ uint32_t pack2(fp16 a, fp16 b)
{
    return (uint32_t)__half_as_ushort(a) | ((uint32_t)__half_as_ushort(b) << 16);
}
#define MMA_F16(d, a0, a1, a2, a3, b0, b1)                                    \
    asm volatile(                                                             \
        "mma.sync.aligned.m16n8k16.row.col.f32.f16.f16.f32 "                  \
        "{%0,%1,%2,%3},{%4,%5,%6,%7},{%8,%9},{%0,%1,%2,%3};"                  \
        : "+f"(d[0]), "+f"(d[1]), "+f"(d[2]), "+f"(d[3])                      \
        : "r"(a0), "r"(a1), "r"(a2), "r"(a3), "r"(b0), "r"(b1))

#define LDSM_X4(r0, r1, r2, r3, addr)                                         \
    asm volatile("ldmatrix.sync.aligned.m8n8.x4.shared.b16 {%0,%1,%2,%3}, [%4];" \
        : "=r"(r0), "=r"(r1), "=r"(r2), "=r"(r3) : "r"(addr))

#define CPA16(dst, src) \
    asm volatile("cp.async.cg.shared.global [%0], [%1], 16;" :: "r"(dst), "l"(src))

// ---------------- elementwise split of feats ----------------
__global__ __launch_bounds__(256) void convert_feats(const float* __restrict__ fp,
                                                     const float* __restrict__ fs)
{
    size_t i = (size_t)blockIdx.x * 256 + threadIdx.x;
    const float4 v = ((const float4*)(blockIdx.y ? fs : fp))[i];
    fp16* Hh = (fp16*)(g_buf + (blockIdx.y ? OFF_FS_HI : OFF_FP_HI));
    fp16* Hl = (fp16*)(g_buf + (blockIdx.y ? OFF_FS_LO : OFF_FP_LO));
    fp16 h0, l0, h1, l1, h2, l2, h3, l3;
    split_fp(v.x, h0, l0); split_fp(v.y, h1, l1);
    split_fp(v.z, h2, l2); split_fp(v.w, h3, l3);
    ((uint2*)Hh)[i] = make_uint2(pack2(h0, h1), pack2(h2, h3));
    ((uint2*)Hl)[i] = make_uint2(pack2(l0, l1), pack2(l2, l3));
}

// ---------------- transpose W (512x512) -> Wt hi/lo ----------------
__global__ void transpose_w(const float* __restrict__ W)
{
    __shared__ float s[32][33];
    int k = blockIdx.y * 32 + threadIdx.y;
    int n = blockIdx.x * 32 + threadIdx.x;
    s[threadIdx.y][threadIdx.x] = W[k * KD + n];
    __syncthreads();
    int nn = blockIdx.x * 32 + threadIdx.y;
    int kk = blockIdx.y * 32 + threadIdx.x;
    float v = s[threadIdx.x][threadIdx.y];
    fp16 h, l; split_fp(v, h, l);
    ((fp16*)(g_buf + OFF_WT_HI))[nn * KD + kk] = h;
    ((fp16*)(g_buf + OFF_WT_LO))[nn * KD + kk] = l;
}

// ---------------- transpose feat_s (8192x512) -> Vt hi (512x8192) ------------
__global__ void transpose_vs(const float* __restrict__ fs)
{
    __shared__ float s[32][33];
    int k = blockIdx.y * 32 + threadIdx.y;
    int n = blockIdx.x * 32 + threadIdx.x;
    s[threadIdx.y][threadIdx.x] = fs[(size_t)k * KD + n];
    __syncthreads();
    int nn = blockIdx.x * 32 + threadIdx.y;
    int kk = blockIdx.y * 32 + threadIdx.x;
    float v = s[threadIdx.x][threadIdx.y];
    ((fp16*)(g_buf + OFF_VT_HI))[(size_t)nn * NR + kk] = __float2half(v);
}

// ---------------- unified GEMM: D[128,128] tile = A[128,K] * B[128,K]^T ------
// fp16 split. NPROD=1: A_hi*B_hi                  (S and C GEMMs)
//             NPROD=3: A_hi*(B_hi+B_lo)+A_lo*B_hi (proj, near-exact)
// 512 threads, warp grid 4x4 (warp tile 32x32); ldmatrix; 3-stage cp.async.
extern __shared__ char s_raw[];

template <int MODE, int NPROD, int LDA, int LDB, int KTILES, int LDO, bool ACCUM>
__global__ __launch_bounds__(NTHREADS, 1) void gemm_kernel(
    const fp16* __restrict__ Ahi, const fp16* __restrict__ Alo,
    const fp16* __restrict__ Bhi, const fp16* __restrict__ Blo,
    fp16* __restrict__ Ohi, fp16* __restrict__ Olo,
    float* __restrict__ Of, int part_off)
{
    fp16* smbase = (fp16*)s_raw;
    const int tid = threadIdx.x, lane = tid & 31, warp = tid >> 5;
    const int wm = (warp >> 2) * 32;
    const int wn = (warp & 3) * 32;
    const int m0 = blockIdx.y * 128, n0 = blockIdx.x * 128;

    // loader: 128 rows, 4 threads/row, 1x16B per thread per region
    const int ra = tid >> 2, ca = (tid & 3) * 8;
    const fp16* pAh = Ahi + (size_t)(m0 + ra) * LDA + ca;
    const fp16* pAl = Alo + (size_t)(m0 + ra) * LDA + ca;
    const fp16* pBh = Bhi + (size_t)(n0 + ra) * LDB + ca;
    const fp16* pBl = Blo + (size_t)(n0 + ra) * LDB + ca;
    const uint32_t sbase = (uint32_t)__cvta_generic_to_shared(smbase);
    const uint32_t oAh = sbase + (uint32_t)(ra * 40 + ca) * 2;
    const uint32_t oAl = oAh + 10240;
    const uint32_t oBh = oAh + 20480;
    const uint32_t oBl = oAh + 30720;

    auto load_stage = [&](int st, int kt) {
        const uint32_t s = (uint32_t)st * STAGE_BYTES;
        const int ko = kt * 32;
        CPA16(oAh + s, pAh + ko);
        CPA16(oBh + s, pBh + ko);
        if (NPROD == 3) {
            CPA16(oAl + s, pAl + ko);
            CPA16(oBl + s, pBl + ko);
        }
    };

    // ldmatrix lane address components (bytes)
    const uint32_t laneA = (uint32_t)((wm + (lane & 15)) * 40 + ((lane >> 4) * 8)) * 2;
    const uint32_t laneB = (uint32_t)((wn + ((lane >> 4) * 8) + (lane & 7)) * 40
                                      + (((lane >> 3) & 1) * 8)) * 2 + 20480;

    float acc[2][4][4];
    #pragma unroll
    for (int a = 0; a < 2; a++)
        #pragma unroll
        for (int b = 0; b < 4; b++)
            #pragma unroll
            for (int c = 0; c < 4; c++) acc[a][b][c] = 0.f;

    load_stage(0, 0);
    asm volatile("cp.async.commit_group;");
    load_stage(1, 1);
    asm volatile("cp.async.commit_group;");

    int stage = 0;
    for (int kt = 0; kt < KTILES; kt++) {
        asm volatile("cp.async.wait_group 1;");
        __syncthreads();
        if (kt + 2 < KTILES)
            load_stage((stage + 2) % NSTAGE, kt + 2);
        asm volatile("cp.async.commit_group;");

        const uint32_t sb = sbase + (uint32_t)stage * STAGE_BYTES;
        const uint32_t aA = sb + laneA;
        const uint32_t aB = sb + laneB;
        #pragma unroll
        for (int s = 0; s < 2; s++) {
            const uint32_t so = (uint32_t)s * 32;
            uint32_t bh[4][2], af[2][4];

            LDSM_X4(bh[0][0], bh[0][1], bh[1][0], bh[1][1], aB + so);
            LDSM_X4(bh[2][0], bh[2][1], bh[3][0], bh[3][1], aB + so + 1280);
            #pragma unroll
            for (int mi = 0; mi < 2; mi++)
                LDSM_X4(af[mi][0], af[mi][1], af[mi][2], af[mi][3],
                        aA + so + (uint32_t)mi * 1280);

            if (NPROD == 1) {
                #pragma unroll
                for (int ni = 0; ni < 4; ni++)
                    #pragma unroll
                    for (int mi = 0; mi < 2; mi++)
                        MMA_F16(acc[mi][ni], af[mi][0], af[mi][1], af[mi][2], af[mi][3],
                                bh[ni][0], bh[ni][1]);
            } else {
                uint32_t bl[4][2];
                LDSM_X4(bl[0][0], bl[0][1], bl[1][0], bl[1][1], aB + so + 10240);
                LDSM_X4(bl[2][0], bl[2][1], bl[3][0], bl[3][1], aB + so + 10240 + 1280);
                #pragma unroll
                for (int ni = 0; ni < 4; ni++)
                    #pragma unroll
                    for (int mi = 0; mi < 2; mi++) {
                        MMA_F16(acc[mi][ni], af[mi][0], af[mi][1], af[mi][2], af[mi][3],
                                bh[ni][0], bh[ni][1]);
                        MMA_F16(acc[mi][ni], af[mi][0], af[mi][1], af[mi][2], af[mi][3],
                                bl[ni][0], bl[ni][1]);
                    }
                // A_lo * B_hi
                #pragma unroll
                for (int mi = 0; mi < 2; mi++)
                    LDSM_X4(af[mi][0], af[mi][1], af[mi][2], af[mi][3],
                            aA + so + 10240 + (uint32_t)mi * 1280);
                #pragma unroll
                for (int ni = 0; ni < 4; ni++)
                    #pragma unroll
                    for (int mi = 0; mi < 2; mi++)
                        MMA_F16(acc[mi][ni], af[mi][0], af[mi][1], af[mi][2], af[mi][3],
                                bh[ni][0], bh[ni][1]);
            }
        }
        stage = (stage + 1 == NSTAGE) ? 0 : stage + 1;
    }

    // ---------------- epilogue ----------------
    float s2 = 0.f;
    #pragma unroll
    for (int mi = 0; mi < 2; mi++)
        #pragma unroll
        for (int ni = 0; ni < 4; ni++) {
            const int m = m0 + wm + mi * 16 + (lane >> 2);
            const int n = n0 + wn + ni * 8 + (lane & 3) * 2;
            float v0 = acc[mi][ni][0], v1 = acc[mi][ni][1];
            float v2 = acc[mi][ni][2], v3 = acc[mi][ni][3];
            if constexpr (MODE == 1) {
                // relu + sumsq + store S_hi
                v0 = fmaxf(v0, 0.f); v1 = fmaxf(v1, 0.f);
                v2 = fmaxf(v2, 0.f); v3 = fmaxf(v3, 0.f);
                s2 = fmaf(v0, v0, s2); s2 = fmaf(v1, v1, s2);
                s2 = fmaf(v2, v2, s2); s2 = fmaf(v3, v3, s2);
                *(uint32_t*)&Ohi[(size_t)m * LDO + n] =
                    pack2(__float2half(v0), __float2half(v1));
                *(uint32_t*)&Ohi[(size_t)(m + 8) * LDO + n] =
                    pack2(__float2half(v2), __float2half(v3));
            } else if constexpr (MODE == 2) {
                float2* p0 = (float2*)&Of[(size_t)m * LDO + n];
                float2* p1 = (float2*)&Of[(size_t)(m + 8) * LDO + n];
                if constexpr (ACCUM) {
                    float2 o0 = *p0, o1 = *p1;
                    *p0 = make_float2(o0.x + v0, o0.y + v1);
                    *p1 = make_float2(o1.x + v2, o1.y + v3);
                } else {
                    *p0 = make_float2(v0, v1);
                    *p1 = make_float2(v2, v3);
                }
            } else {
                fp16 h0, l0, h1, l1;
                split_fp(v0, h0, l0); split_fp(v1, h1, l1);
                *(uint32_t*)&Ohi[(size_t)m * LDO + n] = pack2(h0, h1);
                *(uint32_t*)&Olo[(size_t)m * LDO + n] = pack2(l0, l1);
                split_fp(v2, h0, l0); split_fp(v3, h1, l1);
                *(uint32_t*)&Ohi[(size_t)(m + 8) * LDO + n] = pack2(h0, h1);
                *(uint32_t*)&Olo[(size_t)(m + 8) * LDO + n] = pack2(l0, l1);
            }
        }

    if constexpr (MODE == 1) {
        __syncthreads();
        float* sf = (float*)s_raw;
        sf[tid] = s2;
        __syncthreads();
        #pragma unroll
        for (int off = 256; off > 0; off >>= 1) {
            if (tid < off) sf[tid] += sf[tid + off];
            __syncthreads();
        }
        if (tid == 0) g_part[part_off + blockIdx.y * gridDim.x + blockIdx.x] = sf[0];
    }
}

// ---------------- reduce NPART partials -> 1/fro -----------------------------
__global__ void reduce_kernel()
{
    __shared__ float rs[1024];
    int t = threadIdx.x;
    float v = 0.f;
    #pragma unroll
    for (int i = 0; i < NPART / 1024; i++) v += g_part[t + 1024 * i];
    rs[t] = v;
    __syncthreads();
    #pragma unroll
    for (int off = 512; off > 0; off >>= 1) {
        if (t < off) rs[t] += rs[t + off];
        __syncthreads();
    }
    if (t == 0) g_scale[0] = 1.0f / sqrtf(rs[0]);
}

// ---------------- scale output in place --------------------------------------
__global__ __launch_bounds__(256) void scale_kernel(float* __restrict__ out)
{
    const float s = g_scale[0];
    size_t i = (size_t)blockIdx.x * blockDim.x + threadIdx.x;
    float4* o = (float4*)out;
    float4 v = o[i];
    v.x *= s; v.y *= s; v.z *= s; v.w *= s;
    o[i] = v;
}

// ---------------- launch ----------------
extern "C" void kernel_launch(void* const* d_in, const int* in_sizes, int n_in,
                              void* d_out, int out_size)
{
    (void)in_sizes; (void)n_in; (void)out_size;
    const float* feat_p = (const float*)d_in[0];
    const float* feat_s = (const float*)d_in[1];
    const float* weight = (const float*)d_in[2];
    float* out = (float*)d_out;

    void* basep = nullptr;
    cudaGetSymbolAddress(&basep, g_buf);
    char* base = (char*)basep;
    fp16* Fp_hi = (fp16*)(base + OFF_FP_HI);
    fp16* Fp_lo = (fp16*)(base + OFF_FP_LO);
    fp16* Fs_hi = (fp16*)(base + OFF_FS_HI);
    fp16* Fs_lo = (fp16*)(base + OFF_FS_LO);
    fp16* S_hi  = (fp16*)(base + OFF_S_HI);
    fp16* Wt_hi = (fp16*)(base + OFF_WT_HI);
    fp16* Wt_lo = (fp16*)(base + OFF_WT_LO);
    fp16* Hp_hi = (fp16*)(base + OFF_HP_HI);
    fp16* Hp_lo = (fp16*)(base + OFF_HP_LO);
    fp16* Hs_hi = (fp16*)(base + OFF_HS_HI);
    fp16* Hs_lo = (fp16*)(base + OFF_HS_LO);
    fp16* Vt_hi = (fp16*)(base + OFF_VT_HI);

    cudaFuncSetAttribute(gemm_kernel<0, 3, 512, 512, 16, 512, false>,
                         cudaFuncAttributeMaxDynamicSharedMemorySize, SMEMSZ);
    cudaFuncSetAttribute(gemm_kernel<1, 1, 512, 512, 16, CHUNK, false>,
                         cudaFuncAttributeMaxDynamicSharedMemorySize, SMEMSZ);
    cudaFuncSetAttribute(gemm_kernel<2, 1, CHUNK, NR, CHUNK / 32, 512, false>,
                         cudaFuncAttributeMaxDynamicSharedMemorySize, SMEMSZ);
    cudaFuncSetAttribute(gemm_kernel<2, 1, CHUNK, NR, CHUNK / 32, 512, true>,
                         cudaFuncAttributeMaxDynamicSharedMemorySize, SMEMSZ);

    convert_feats<<<dim3(NR * KD / 4 / 256, 2), 256>>>(feat_p, feat_s);
    transpose_w<<<dim3(16, 16), dim3(32, 32)>>>(weight);
    transpose_vs<<<dim3(16, 256), dim3(32, 32)>>>(feat_s);

    // proj (3-term, near-exact): M=8192 N=512 K=512
    gemm_kernel<0, 3, 512, 512, 16, 512, false><<<dim3(4, 64), NTHREADS, SMEMSZ>>>(
        Fp_hi, Fp_lo, Wt_hi, Wt_lo, Hp_hi, Hp_lo, nullptr, 0);
    gemm_kernel<0, 3, 512, 512, 16, 512, false><<<dim3(4, 64), NTHREADS, SMEMSZ>>>(
        Fs_hi, Fs_lo, Wt_hi, Wt_lo, Hs_hi, Hs_lo, nullptr, 0);

    // chunked S + C accumulation (1-term fp16)
    for (int c = 0; c < NCHUNK; c++) {
        const int j0 = c * CHUNK;
        gemm_kernel<1, 1, 512, 512, 16, CHUNK, false><<<dim3(CHUNK / 128, 64), NTHREADS, SMEMSZ>>>(
            Hp_hi, nullptr, Hs_hi + (size_t)j0 * 512, nullptr,
            S_hi, nullptr, nullptr, c * (CHUNK / 128) * 64);
        if (c == 0)
            gemm_kernel<2, 1, CHUNK, NR, CHUNK / 32, 512, false><<<dim3(4, 64), NTHREADS, SMEMSZ>>>(
                S_hi, nullptr, Vt_hi + j0, nullptr, nullptr, nullptr, out, 0);
        else
            gemm_kernel<2, 1, CHUNK, NR, CHUNK / 32, 512, true><<<dim3(4, 64), NTHREADS, SMEMSZ>>>(
                S_hi, nullptr, Vt_hi + j0, nullptr, nullptr, nullptr, out, 0);
    }

    reduce_kernel<<<1, 1024>>>();
    scale_kernel<<<(NR * KD) / (4 * 256), 256>>>(out);
}

// round 15
// speedup vs baseline: 2.7350x; 1.0332x over previous
#include <cuda_runtime.h>
#include <cuda_fp16.h>
#include <cstdint>

typedef __half fp16;

#define KD  512
#define NR  8192
#define CHUNK 2048
#define NCHUNK (NR / CHUNK)                  // 4
#define NPART (NCHUNK * (CHUNK / 256) * 64)  // 2048

#define NTHREADS 512
#define NSTAGE 3
#define SMEM_PROJ (40960 * NSTAGE)   // 122880
#define SMEM_1T   (30720 * NSTAGE)   // 92160
#define MB (1024 * 1024)

// ---- single scratch buffer (81 MB total statics — proven safe) ----
// S_hi (32 MB) overlays Fp_hi/Fp_lo/Fs_hi/Fs_lo (dead after proj)
#define OFF_FP_HI  (0 * MB)
#define OFF_FP_LO  (8 * MB)
#define OFF_FS_HI  (16 * MB)
#define OFF_FS_LO  (24 * MB)
#define OFF_S_HI   (0 * MB)
#define OFF_WT_HI  (32 * MB)
#define OFF_WT_LO  (32 * MB + 512 * 1024)
#define OFF_HP_HI  (33 * MB)
#define OFF_HP_LO  (41 * MB)
#define OFF_HS_HI  (49 * MB)
#define OFF_HS_LO  (57 * MB)
#define OFF_VT_HI  (65 * MB)
#define BUF_BYTES  (81 * MB)

__device__ __align__(1024) char g_buf[BUF_BYTES];
__device__ float g_part[NPART];
__device__ float g_scale[1];

// ---------------- helpers ----------------
__device__ __forceinline__ void split_fp(float v, fp16& hi, fp16& lo)
{
    hi = __float2half(v);
    lo = __float2half(v - __half2float(hi));
}
__device__ __forceinline__ uint32_t pack2(fp16 a, fp16 b)
{
    return (uint32_t)__half_as_ushort(a) | ((uint32_t)__half_as_ushort(b) << 16);
}
#define MMA_F16(d, a0, a1, a2, a3, b0, b1)                                    \
    asm volatile(                                                             \
        "mma.sync.aligned.m16n8k16.row.col.f32.f16.f16.f32 "                  \
        "{%0,%1,%2,%3},{%4,%5,%6,%7},{%8,%9},{%0,%1,%2,%3};"                  \
        : "+f"(d[0]), "+f"(d[1]), "+f"(d[2]), "+f"(d[3])                      \
        : "r"(a0), "r"(a1), "r"(a2), "r"(a3), "r"(b0), "r"(b1))

#define LDSM_X4(r0, r1, r2, r3, addr)                                         \
    asm volatile("ldmatrix.sync.aligned.m8n8.x4.shared.b16 {%0,%1,%2,%3}, [%4];" \
        : "=r"(r0), "=r"(r1), "=r"(r2), "=r"(r3) : "r"(addr))

#define CPA16(dst, src) \
    asm volatile("cp.async.cg.shared.global [%0], [%1], 16;" :: "r"(dst), "l"(src))

// ---------------- elementwise split of feats ----------------
__global__ __launch_bounds__(256) void convert_feats(const float* __restrict__ fp,
                                                     const float* __restrict__ fs)
{
    size_t i = (size_t)blockIdx.x * 256 + threadIdx.x;
    const float4 v = ((const float4*)(blockIdx.y ? fs : fp))[i];
    fp16* Hh = (fp16*)(g_buf + (blockIdx.y ? OFF_FS_HI : OFF_FP_HI));
    fp16* Hl = (fp16*)(g_buf + (blockIdx.y ? OFF_FS_LO : OFF_FP_LO));
    fp16 h0, l0, h1, l1, h2, l2, h3, l3;
    split_fp(v.x, h0, l0); split_fp(v.y, h1, l1);
    split_fp(v.z, h2, l2); split_fp(v.w, h3, l3);
    ((uint2*)Hh)[i] = make_uint2(pack2(h0, h1), pack2(h2, h3));
    ((uint2*)Hl)[i] = make_uint2(pack2(l0, l1), pack2(l2, l3));
}

// ---------------- transpose W (512x512) -> Wt hi/lo ----------------
__global__ void transpose_w(const float* __restrict__ W)
{
    __shared__ float s[32][33];
    int k = blockIdx.y * 32 + threadIdx.y;
    int n = blockIdx.x * 32 + threadIdx.x;
    s[threadIdx.y][threadIdx.x] = W[k * KD + n];
    __syncthreads();
    int nn = blockIdx.x * 32 + threadIdx.y;
    int kk = blockIdx.y * 32 + threadIdx.x;
    float v = s[threadIdx.x][threadIdx.y];
    fp16 h, l; split_fp(v, h, l);
    ((fp16*)(g_buf + OFF_WT_HI))[nn * KD + kk] = h;
    ((fp16*)(g_buf + OFF_WT_LO))[nn * KD + kk] = l;
}

// ---------------- transpose feat_s (8192x512) -> Vt hi (512x8192) ------------
__global__ void transpose_vs(const float* __restrict__ fs)
{
    __shared__ float s[32][33];
    int k = blockIdx.y * 32 + threadIdx.y;
    int n = blockIdx.x * 32 + threadIdx.x;
    s[threadIdx.y][threadIdx.x] = fs[(size_t)k * KD + n];
    __syncthreads();
    int nn = blockIdx.x * 32 + threadIdx.y;
    int kk = blockIdx.y * 32 + threadIdx.x;
    float v = s[threadIdx.x][threadIdx.y];
    ((fp16*)(g_buf + OFF_VT_HI))[(size_t)nn * NR + kk] = __float2half(v);
}

// ---------------- unified GEMM: D[128,BN] tile = A[128,K] * B[BN,K]^T --------
// NPROD=3 (BN=128): A_hi*(B_hi+B_lo)+A_lo*B_hi  (proj, near-exact)
//   stage: Ahi@0 Alo@10240 Bhi@20480 Blo@30720 (40960 B)
// NPROD=1 (BN=256): A_hi*B_hi  (S, C)
//   stage: Ahi@0 (10240) Bhi@10240 (20480) = 30720 B
// 512 threads, warp grid 4x4; ldmatrix; 3-stage cp.async.
extern __shared__ char s_raw[];

template <int MODE, int NPROD, int BN, int LDA, int LDB, int KTILES, int LDO, bool ACCUM>
__global__ __launch_bounds__(NTHREADS, 1) void gemm_kernel(
    const fp16* __restrict__ Ahi, const fp16* __restrict__ Alo,
    const fp16* __restrict__ Bhi, const fp16* __restrict__ Blo,
    fp16* __restrict__ Ohi, fp16* __restrict__ Olo,
    float* __restrict__ Of, int part_off)
{
    constexpr int STB   = (BN == 256) ? 30720 : 40960;
    constexpr int BOFF  = (BN == 256) ? 10240 : 20480;
    constexpr int NI    = BN / 32;      // n8-tiles per warp: 8 or 4

    fp16* smbase = (fp16*)s_raw;
    const int tid = threadIdx.x, lane = tid & 31, warp = tid >> 5;
    const int wm = (warp >> 2) * 32;
    const int wn = (warp & 3) * (BN / 4);
    const int m0 = blockIdx.y * 128, n0 = blockIdx.x * BN;

    const uint32_t sbase = (uint32_t)__cvta_generic_to_shared(smbase);

    // ---- loader geometry ----
    // A: 128 rows x 4 chunks; 1 chunk/thread
    const int raA = tid >> 2, caA = (tid & 3) * 8;
    const fp16* pAh = Ahi + (size_t)(m0 + raA) * LDA + caA;
    const fp16* pAl = (NPROD == 3) ? Alo + (size_t)(m0 + raA) * LDA + caA : nullptr;
    const uint32_t oAh = sbase + (uint32_t)(raA * 40 + caA) * 2;
    // B: BN rows. BN=128: 4 thr/row 1 chunk; BN=256: 2 thr/row 2 chunks
    const int rB  = (BN == 256) ? (tid >> 1) : (tid >> 2);
    const int cB  = (BN == 256) ? ((tid & 1) * 16) : ((tid & 3) * 8);
    const fp16* pBh = Bhi + (size_t)(n0 + rB) * LDB + cB;
    const fp16* pBl = (NPROD == 3) ? Blo + (size_t)(n0 + rB) * LDB + cB : nullptr;
    const uint32_t oBh = sbase + BOFF + (uint32_t)(rB * 40 + cB) * 2;

    auto load_stage = [&](int st, int kt) {
        const uint32_t s = (uint32_t)st * STB;
        const int ko = kt * 32;
        CPA16(oAh + s, pAh + ko);
        CPA16(oBh + s, pBh + ko);
        if (BN == 256) CPA16(oBh + s + 16, pBh + ko + 8);
        if (NPROD == 3) {
            CPA16(oAh + s + 10240, pAl + ko);
            CPA16(oBh + s + 10240, pBl + ko);
        }
    };

    // ldmatrix lane address components (bytes)
    const uint32_t laneA = (uint32_t)((wm + (lane & 15)) * 40 + ((lane >> 4) * 8)) * 2;
    const uint32_t laneB = (uint32_t)((wn + ((lane >> 4) * 8) + (lane & 7)) * 40
                                      + (((lane >> 3) & 1) * 8)) * 2 + BOFF;

    float acc[2][NI][4];
    #pragma unroll
    for (int a = 0; a < 2; a++)
        #pragma unroll
        for (int b = 0; b < NI; b++)
            #pragma unroll
            for (int c = 0; c < 4; c++) acc[a][b][c] = 0.f;

    load_stage(0, 0);
    asm volatile("cp.async.commit_group;");
    load_stage(1, 1);
    asm volatile("cp.async.commit_group;");

    int stage = 0;
    for (int kt = 0; kt < KTILES; kt++) {
        asm volatile("cp.async.wait_group 1;");
        __syncthreads();
        if (kt + 2 < KTILES)
            load_stage((stage + 2) % NSTAGE, kt + 2);
        asm volatile("cp.async.commit_group;");

        const uint32_t sb = sbase + (uint32_t)stage * STB;
        const uint32_t aA = sb + laneA;
        const uint32_t aB = sb + laneB;
        #pragma unroll
        for (int s = 0; s < 2; s++) {
            const uint32_t so = (uint32_t)s * 32;
            uint32_t af[2][4];

            #pragma unroll
            for (int mi = 0; mi < 2; mi++)
                LDSM_X4(af[mi][0], af[mi][1], af[mi][2], af[mi][3],
                        aA + so + (uint32_t)mi * 1280);

            // hi*hi products, one B ldmatrix.x4 (2 n-tiles) at a time
            #pragma unroll
            for (int p = 0; p < NI / 2; p++) {
                uint32_t b0, b1, b2, b3;
                LDSM_X4(b0, b1, b2, b3, aB + so + (uint32_t)p * 1280);
                #pragma unroll
                for (int mi = 0; mi < 2; mi++) {
                    MMA_F16(acc[mi][2 * p],     af[mi][0], af[mi][1], af[mi][2], af[mi][3], b0, b1);
                    MMA_F16(acc[mi][2 * p + 1], af[mi][0], af[mi][1], af[mi][2], af[mi][3], b2, b3);
                }
            }

            if (NPROD == 3) {
                // hi*lo
                #pragma unroll
                for (int p = 0; p < NI / 2; p++) {
                    uint32_t b0, b1, b2, b3;
                    LDSM_X4(b0, b1, b2, b3, aB + so + 10240 + (uint32_t)p * 1280);
                    #pragma unroll
                    for (int mi = 0; mi < 2; mi++) {
                        MMA_F16(acc[mi][2 * p],     af[mi][0], af[mi][1], af[mi][2], af[mi][3], b0, b1);
                        MMA_F16(acc[mi][2 * p + 1], af[mi][0], af[mi][1], af[mi][2], af[mi][3], b2, b3);
                    }
                }
                // lo*hi
                #pragma unroll
                for (int mi = 0; mi < 2; mi++)
                    LDSM_X4(af[mi][0], af[mi][1], af[mi][2], af[mi][3],
                            aA + so + 10240 + (uint32_t)mi * 1280);
                #pragma unroll
                for (int p = 0; p < NI / 2; p++) {
                    uint32_t b0, b1, b2, b3;
                    LDSM_X4(b0, b1, b2, b3, aB + so + (uint32_t)p * 1280);
                    #pragma unroll
                    for (int mi = 0; mi < 2; mi++) {
                        MMA_F16(acc[mi][2 * p],     af[mi][0], af[mi][1], af[mi][2], af[mi][3], b0, b1);
                        MMA_F16(acc[mi][2 * p + 1], af[mi][0], af[mi][1], af[mi][2], af[mi][3], b2, b3);
                    }
                }
            }
        }
        stage = (stage + 1 == NSTAGE) ? 0 : stage + 1;
    }

    // ---------------- epilogue ----------------
    float s2 = 0.f;
    #pragma unroll
    for (int mi = 0; mi < 2; mi++)
        #pragma unroll
        for (int ni = 0; ni < NI; ni++) {
            const int m = m0 + wm + mi * 16 + (lane >> 2);
            const int n = n0 + wn + ni * 8 + (lane & 3) * 2;
            float v0 = acc[mi][ni][0], v1 = acc[mi][ni][1];
            float v2 = acc[mi][ni][2], v3 = acc[mi][ni][3];
            if constexpr (MODE == 1) {
                v0 = fmaxf(v0, 0.f); v1 = fmaxf(v1, 0.f);
                v2 = fmaxf(v2, 0.f); v3 = fmaxf(v3, 0.f);
                s2 = fmaf(v0, v0, s2); s2 = fmaf(v1, v1, s2);
                s2 = fmaf(v2, v2, s2); s2 = fmaf(v3, v3, s2);
                *(uint32_t*)&Ohi[(size_t)m * LDO + n] =
                    pack2(__float2half(v0), __float2half(v1));
                *(uint32_t*)&Ohi[(size_t)(m + 8) * LDO + n] =
                    pack2(__float2half(v2), __float2half(v3));
            } else if constexpr (MODE == 2) {
                float2* p0 = (float2*)&Of[(size_t)m * LDO + n];
                float2* p1 = (float2*)&Of[(size_t)(m + 8) * LDO + n];
                if constexpr (ACCUM) {
                    float2 o0 = *p0, o1 = *p1;
                    *p0 = make_float2(o0.x + v0, o0.y + v1);
                    *p1 = make_float2(o1.x + v2, o1.y + v3);
                } else {
                    *p0 = make_float2(v0, v1);
                    *p1 = make_float2(v2, v3);
                }
            } else {
                fp16 h0, l0, h1, l1;
                split_fp(v0, h0, l0); split_fp(v1, h1, l1);
                *(uint32_t*)&Ohi[(size_t)m * LDO + n] = pack2(h0, h1);
                *(uint32_t*)&Olo[(size_t)m * LDO + n] = pack2(l0, l1);
                split_fp(v2, h0, l0); split_fp(v3, h1, l1);
                *(uint32_t*)&Ohi[(size_t)(m + 8) * LDO + n] = pack2(h0, h1);
                *(uint32_t*)&Olo[(size_t)(m + 8) * LDO + n] = pack2(l0, l1);
            }
        }

    if constexpr (MODE == 1) {
        __syncthreads();
        float* sf = (float*)s_raw;
        sf[tid] = s2;
        __syncthreads();
        #pragma unroll
        for (int off = 256; off > 0; off >>= 1) {
            if (tid < off) sf[tid] += sf[tid + off];
            __syncthreads();
        }
        if (tid == 0) g_part[part_off + blockIdx.y * gridDim.x + blockIdx.x] = sf[0];
    }
}

// ---------------- reduce NPART partials -> 1/fro -----------------------------
__global__ void reduce_kernel()
{
    __shared__ float rs[1024];
    int t = threadIdx.x;
    float v = 0.f;
    #pragma unroll
    for (int i = 0; i < NPART / 1024; i++) v += g_part[t + 1024 * i];
    rs[t] = v;
    __syncthreads();
    #pragma unroll
    for (int off = 512; off > 0; off >>= 1) {
        if (t < off) rs[t] += rs[t + off];
        __syncthreads();
    }
    if (t == 0) g_scale[0] = 1.0f / sqrtf(rs[0]);
}

// ---------------- scale output in place --------------------------------------
__global__ __launch_bounds__(256) void scale_kernel(float* __restrict__ out)
{
    const float s = g_scale[0];
    size_t i = (size_t)blockIdx.x * blockDim.x + threadIdx.x;
    float4* o = (float4*)out;
    float4 v = o[i];
    v.x *= s; v.y *= s; v.z *= s; v.w *= s;
    o[i] = v;
}

// ---------------- launch ----------------
extern "C" void kernel_launch(void* const* d_in, const int* in_sizes, int n_in,
                              void* d_out, int out_size)
{
    (void)in_sizes; (void)n_in; (void)out_size;
    const float* feat_p = (const float*)d_in[0];
    const float* feat_s = (const float*)d_in[1];
    const float* weight = (const float*)d_in[2];
    float* out = (float*)d_out;

    void* basep = nullptr;
    cudaGetSymbolAddress(&basep, g_buf);
    char* base = (char*)basep;
    fp16* Fp_hi = (fp16*)(base + OFF_FP_HI);
    fp16* Fp_lo = (fp16*)(base + OFF_FP_LO);
    fp16* Fs_hi = (fp16*)(base + OFF_FS_HI);
    fp16* Fs_lo = (fp16*)(base + OFF_FS_LO);
    fp16* S_hi  = (fp16*)(base + OFF_S_HI);
    fp16* Wt_hi = (fp16*)(base + OFF_WT_HI);
    fp16* Wt_lo = (fp16*)(base + OFF_WT_LO);
    fp16* Hp_hi = (fp16*)(base + OFF_HP_HI);
    fp16* Hp_lo = (fp16*)(base + OFF_HP_LO);
    fp16* Hs_hi = (fp16*)(base + OFF_HS_HI);
    fp16* Hs_lo = (fp16*)(base + OFF_HS_LO);
    fp16* Vt_hi = (fp16*)(base + OFF_VT_HI);

    cudaFuncSetAttribute(gemm_kernel<0, 3, 128, 512, 512, 16, 512, false>,
                         cudaFuncAttributeMaxDynamicSharedMemorySize, SMEM_PROJ);
    cudaFuncSetAttribute(gemm_kernel<1, 1, 256, 512, 512, 16, CHUNK, false>,
                         cudaFuncAttributeMaxDynamicSharedMemorySize, SMEM_1T);
    cudaFuncSetAttribute(gemm_kernel<2, 1, 256, CHUNK, NR, CHUNK / 32, 512, false>,
                         cudaFuncAttributeMaxDynamicSharedMemorySize, SMEM_1T);
    cudaFuncSetAttribute(gemm_kernel<2, 1, 256, CHUNK, NR, CHUNK / 32, 512, true>,
                         cudaFuncAttributeMaxDynamicSharedMemorySize, SMEM_1T);

    convert_feats<<<dim3(NR * KD / 4 / 256, 2), 256>>>(feat_p, feat_s);
    transpose_w<<<dim3(16, 16), dim3(32, 32)>>>(weight);
    transpose_vs<<<dim3(16, 256), dim3(32, 32)>>>(feat_s);

    // proj (3-term, near-exact): M=8192 N=512 K=512
    gemm_kernel<0, 3, 128, 512, 512, 16, 512, false><<<dim3(4, 64), NTHREADS, SMEM_PROJ>>>(
        Fp_hi, Fp_lo, Wt_hi, Wt_lo, Hp_hi, Hp_lo, nullptr, 0);
    gemm_kernel<0, 3, 128, 512, 512, 16, 512, false><<<dim3(4, 64), NTHREADS, SMEM_PROJ>>>(
        Fs_hi, Fs_lo, Wt_hi, Wt_lo, Hs_hi, Hs_lo, nullptr, 0);

    // chunked S + C accumulation (1-term fp16, CHUNK=2048)
    for (int c = 0; c < NCHUNK; c++) {
        const int j0 = c * CHUNK;
        gemm_kernel<1, 1, 256, 512, 512, 16, CHUNK, false>
            <<<dim3(CHUNK / 256, 64), NTHREADS, SMEM_1T>>>(
            Hp_hi, nullptr, Hs_hi + (size_t)j0 * 512, nullptr,
            S_hi, nullptr, nullptr, c * (CHUNK / 256) * 64);
        if (c == 0)
            gemm_kernel<2, 1, 256, CHUNK, NR, CHUNK / 32, 512, false>
                <<<dim3(2, 64), NTHREADS, SMEM_1T>>>(
                S_hi, nullptr, Vt_hi + j0, nullptr, nullptr, nullptr, out, 0);
        else
            gemm_kernel<2, 1, 256, CHUNK, NR, CHUNK / 32, 512, true>
                <<<dim3(2, 64), NTHREADS, SMEM_1T>>>(
                S_hi, nullptr, Vt_hi + j0, nullptr, nullptr, nullptr, out, 0);
    }

    reduce_kernel<<<1, 1024>>>();
    scale_kernel<<<(NR * KD) / (4 * 256), 256>>>(out);
}

// round 17
// speedup vs baseline: 3.2693x; 1.1954x over previous
#include <cuda_runtime.h>
#include <cuda_fp16.h>
#include <cstdint>

typedef __half fp16;

#define KD  512
#define NR  8192
#define CHUNK 4096
#define NCHUNK (NR / CHUNK)                   // 2
#define NPART (NCHUNK * (CHUNK / 256) * 64)   // 2048

#define NTHREADS 512
#define NSTAGE 3
#define STB 30720                     // stage bytes: Ahi 10240 + Bhi 20480
#define SMEMSZ (STB * NSTAGE)         // 92160
#define MB (1024 * 1024)

// ---- single scratch buffer (89 MB total statics) ----
// persistent: Wt@0 Hp@1M Hs@9M Vt@17M ; S chunk @25M (64 MB)
// temp (dead after proj): Fp_hi@25M Fs_hi@33M (inside S region)
#define OFF_WT_HI  (0 * MB)
#define OFF_HP_HI  (1 * MB)
#define OFF_HS_HI  (9 * MB)
#define OFF_VT_HI  (17 * MB)
#define OFF_S_HI   (25 * MB)
#define OFF_FP_HI  (25 * MB)
#define OFF_FS_HI  (33 * MB)
#define BUF_BYTES  (89 * MB)

__device__ __align__(1024) char g_buf[BUF_BYTES];
__device__ float g_part[NPART];
__device__ float g_scale[1];

// ---------------- helpers ----------------
__device__ __forceinline__ uint32_t pack2(fp16 a, fp16 b)
{
    return (uint32_t)__half_as_ushort(a) | ((uint32_t)__half_as_ushort(b) << 16);
}
#define MMA_F16(d, a0, a1, a2, a3, b0, b1)                                    \
    asm volatile(                                                             \
        "mma.sync.aligned.m16n8k16.row.col.f32.f16.f16.f32 "                  \
        "{%0,%1,%2,%3},{%4,%5,%6,%7},{%8,%9},{%0,%1,%2,%3};"                  \
        : "+f"(d[0]), "+f"(d[1]), "+f"(d[2]), "+f"(d[3])                      \
        : "r"(a0), "r"(a1), "r"(a2), "r"(a3), "r"(b0), "r"(b1))

#define LDSM_X4(r0, r1, r2, r3, addr)                                         \
    asm volatile("ldmatrix.sync.aligned.m8n8.x4.shared.b16 {%0,%1,%2,%3}, [%4];" \
        : "=r"(r0), "=r"(r1), "=r"(r2), "=r"(r3) : "r"(addr))

#define CPA16(dst, src) \
    asm volatile("cp.async.cg.shared.global [%0], [%1], 16;" :: "r"(dst), "l"(src))

// ---------------- convert feats -> fp16 (hi only) ----------------
__global__ __launch_bounds__(256) void convert_feats(const float* __restrict__ fp,
                                                     const float* __restrict__ fs)
{
    size_t i = (size_t)blockIdx.x * 256 + threadIdx.x;
    const float4 v = ((const float4*)(blockIdx.y ? fs : fp))[i];
    fp16* Hh = (fp16*)(g_buf + (blockIdx.y ? OFF_FS_HI : OFF_FP_HI));
    ((uint2*)Hh)[i] = make_uint2(
        pack2(__float2half(v.x), __float2half(v.y)),
        pack2(__float2half(v.z), __float2half(v.w)));
}

// ---------------- transpose W (512x512) -> Wt hi ----------------
__global__ void transpose_w(const float* __restrict__ W)
{
    __shared__ float s[32][33];
    int k = blockIdx.y * 32 + threadIdx.y;
    int n = blockIdx.x * 32 + threadIdx.x;
    s[threadIdx.y][threadIdx.x] = W[k * KD + n];
    __syncthreads();
    int nn = blockIdx.x * 32 + threadIdx.y;
    int kk = blockIdx.y * 32 + threadIdx.x;
    ((fp16*)(g_buf + OFF_WT_HI))[nn * KD + kk] = __float2half(s[threadIdx.x][threadIdx.y]);
}

// ---------------- transpose feat_s (8192x512) -> Vt hi (512x8192) ------------
__global__ void transpose_vs(const float* __restrict__ fs)
{
    __shared__ float s[32][33];
    int k = blockIdx.y * 32 + threadIdx.y;
    int n = blockIdx.x * 32 + threadIdx.x;
    s[threadIdx.y][threadIdx.x] = fs[(size_t)k * KD + n];
    __syncthreads();
    int nn = blockIdx.x * 32 + threadIdx.y;
    int kk = blockIdx.y * 32 + threadIdx.x;
    ((fp16*)(g_buf + OFF_VT_HI))[(size_t)nn * NR + kk] = __float2half(s[threadIdx.x][threadIdx.y]);
}

// ---------------- 1-term fp16 GEMM: D[128,256] = A[128,K] * B[256,K]^T -------
// MODE 0: write fp16 (proj)   MODE 1: relu + sumsq + write fp16 (S)
// MODE 2: write f32; ACCUM=true -> (old + v) * g_scale (final C chunk)
// stage: Ahi@0 (10240 B, stride 40h) Bhi@10240 (20480 B); 3 stages.
// 512 threads, warp grid 4x4 (warp tile 32x64); ldmatrix.
extern __shared__ char s_raw[];

template <int MODE, int LDA, int LDB, int KTILES, int LDO, bool ACCUM>
__global__ __launch_bounds__(NTHREADS, 1) void gemm_kernel(
    const fp16* __restrict__ Ahi, const fp16* __restrict__ Bhi,
    fp16* __restrict__ Oh, float* __restrict__ Of, int part_off)
{
    fp16* smbase = (fp16*)s_raw;
    const int tid = threadIdx.x, lane = tid & 31, warp = tid >> 5;
    const int wm = (warp >> 2) * 32;
    const int wn = (warp & 3) * 64;
    const int m0 = blockIdx.y * 128, n0 = blockIdx.x * 256;

    const uint32_t sbase = (uint32_t)__cvta_generic_to_shared(smbase);

    // loaders: A 128 rows x 4 thr/row x 16B ; B 256 rows x 2 thr/row x 2x16B
    const int raA = tid >> 2, caA = (tid & 3) * 8;
    const fp16* pAh = Ahi + (size_t)(m0 + raA) * LDA + caA;
    const uint32_t oAh = sbase + (uint32_t)(raA * 40 + caA) * 2;
    const int rB = tid >> 1, cB = (tid & 1) * 16;
    const fp16* pBh = Bhi + (size_t)(n0 + rB) * LDB + cB;
    const uint32_t oBh = sbase + 10240 + (uint32_t)(rB * 40 + cB) * 2;

    auto load_stage = [&](int st, int kt) {
        const uint32_t s = (uint32_t)st * STB;
        const int ko = kt * 32;
        CPA16(oAh + s, pAh + ko);
        CPA16(oBh + s, pBh + ko);
        CPA16(oBh + s + 16, pBh + ko + 8);
    };

    const uint32_t laneA = (uint32_t)((wm + (lane & 15)) * 40 + ((lane >> 4) * 8)) * 2;
    const uint32_t laneB = (uint32_t)((wn + ((lane >> 4) * 8) + (lane & 7)) * 40
                                      + (((lane >> 3) & 1) * 8)) * 2 + 10240;

    float acc[2][8][4];
    #pragma unroll
    for (int a = 0; a < 2; a++)
        #pragma unroll
        for (int b = 0; b < 8; b++)
            #pragma unroll
            for (int c = 0; c < 4; c++) acc[a][b][c] = 0.f;

    load_stage(0, 0);
    asm volatile("cp.async.commit_group;");
    load_stage(1, 1);
    asm volatile("cp.async.commit_group;");

    int stage = 0;
    for (int kt = 0; kt < KTILES; kt++) {
        asm volatile("cp.async.wait_group 1;");
        __syncthreads();
        if (kt + 2 < KTILES)
            load_stage((stage + 2) % NSTAGE, kt + 2);
        asm volatile("cp.async.commit_group;");

        const uint32_t sb = sbase + (uint32_t)stage * STB;
        const uint32_t aA = sb + laneA;
        const uint32_t aB = sb + laneB;
        #pragma unroll
        for (int s = 0; s < 2; s++) {
            const uint32_t so = (uint32_t)s * 32;
            uint32_t af[2][4];
            #pragma unroll
            for (int mi = 0; mi < 2; mi++)
                LDSM_X4(af[mi][0], af[mi][1], af[mi][2], af[mi][3],
                        aA + so + (uint32_t)mi * 1280);
            #pragma unroll
            for (int p = 0; p < 4; p++) {
                uint32_t b0, b1, b2, b3;
                LDSM_X4(b0, b1, b2, b3, aB + so + (uint32_t)p * 1280);
                #pragma unroll
                for (int mi = 0; mi < 2; mi++) {
                    MMA_F16(acc[mi][2 * p],     af[mi][0], af[mi][1], af[mi][2], af[mi][3], b0, b1);
                    MMA_F16(acc[mi][2 * p + 1], af[mi][0], af[mi][1], af[mi][2], af[mi][3], b2, b3);
                }
            }
        }
        stage = (stage + 1 == NSTAGE) ? 0 : stage + 1;
    }

    // ---------------- epilogue ----------------
    float s2 = 0.f;
    const float sc = (MODE == 2 && ACCUM) ? g_scale[0] : 0.f;
    #pragma unroll
    for (int mi = 0; mi < 2; mi++)
        #pragma unroll
        for (int ni = 0; ni < 8; ni++) {
            const int m = m0 + wm + mi * 16 + (lane >> 2);
            const int n = n0 + wn + ni * 8 + (lane & 3) * 2;
            float v0 = acc[mi][ni][0], v1 = acc[mi][ni][1];
            float v2 = acc[mi][ni][2], v3 = acc[mi][ni][3];
            if constexpr (MODE == 1) {
                v0 = fmaxf(v0, 0.f); v1 = fmaxf(v1, 0.f);
                v2 = fmaxf(v2, 0.f); v3 = fmaxf(v3, 0.f);
                s2 = fmaf(v0, v0, s2); s2 = fmaf(v1, v1, s2);
                s2 = fmaf(v2, v2, s2); s2 = fmaf(v3, v3, s2);
            }
            if constexpr (MODE == 2) {
                float2* p0 = (float2*)&Of[(size_t)m * LDO + n];
                float2* p1 = (float2*)&Of[(size_t)(m + 8) * LDO + n];
                if constexpr (ACCUM) {
                    float2 o0 = *p0, o1 = *p1;
                    *p0 = make_float2((o0.x + v0) * sc, (o0.y + v1) * sc);
                    *p1 = make_float2((o1.x + v2) * sc, (o1.y + v3) * sc);
                } else {
                    *p0 = make_float2(v0, v1);
                    *p1 = make_float2(v2, v3);
                }
            } else if constexpr (MODE != 1) {
                *(uint32_t*)&Oh[(size_t)m * LDO + n] =
                    pack2(__float2half(v0), __float2half(v1));
                *(uint32_t*)&Oh[(size_t)(m + 8) * LDO + n] =
                    pack2(__float2half(v2), __float2half(v3));
            } else {
                ;
            }
            if constexpr (MODE == 1) {
                *(uint32_t*)&Oh[(size_t)m * LDO + n] =
                    pack2(__float2half(v0), __float2half(v1));
                *(uint32_t*)&Oh[(size_t)(m + 8) * LDO + n] =
                    pack2(__float2half(v2), __float2half(v3));
            }
        }

    if constexpr (MODE == 1) {
        __syncthreads();
        float* sf = (float*)s_raw;
        sf[tid] = s2;
        __syncthreads();
        #pragma unroll
        for (int off = 256; off > 0; off >>= 1) {
            if (tid < off) sf[tid] += sf[tid + off];
            __syncthreads();
        }
        if (tid == 0) g_part[part_off + blockIdx.y * gridDim.x + blockIdx.x] = sf[0];
    }
}

// ---------------- reduce NPART partials -> 1/fro -----------------------------
__global__ void reduce_kernel()
{
    __shared__ float rs[1024];
    int t = threadIdx.x;
    float v = 0.f;
    #pragma unroll
    for (int i = 0; i < NPART / 1024; i++) v += g_part[t + 1024 * i];
    rs[t] = v;
    __syncthreads();
    #pragma unroll
    for (int off = 512; off > 0; off >>= 1) {
        if (t < off) rs[t] += rs[t + off];
        __syncthreads();
    }
    if (t == 0) g_scale[0] = 1.0f / sqrtf(rs[0]);
}

// ---------------- launch ----------------
extern "C" void kernel_launch(void* const* d_in, const int* in_sizes, int n_in,
                              void* d_out, int out_size)
{
    (void)in_sizes; (void)n_in; (void)out_size;
    const float* feat_p = (const float*)d_in[0];
    const float* feat_s = (const float*)d_in[1];
    const float* weight = (const float*)d_in[2];
    float* out = (float*)d_out;

    void* basep = nullptr;
    cudaGetSymbolAddress(&basep, g_buf);
    char* base = (char*)basep;
    fp16* Fp_hi = (fp16*)(base + OFF_FP_HI);
    fp16* Fs_hi = (fp16*)(base + OFF_FS_HI);
    fp16* S_hi  = (fp16*)(base + OFF_S_HI);
    fp16* Wt_hi = (fp16*)(base + OFF_WT_HI);
    fp16* Hp_hi = (fp16*)(base + OFF_HP_HI);
    fp16* Hs_hi = (fp16*)(base + OFF_HS_HI);
    fp16* Vt_hi = (fp16*)(base + OFF_VT_HI);

    cudaFuncSetAttribute(gemm_kernel<0, 512, 512, 16, 512, false>,
                         cudaFuncAttributeMaxDynamicSharedMemorySize, SMEMSZ);
    cudaFuncSetAttribute(gemm_kernel<1, 512, 512, 16, CHUNK, false>,
                         cudaFuncAttributeMaxDynamicSharedMemorySize, SMEMSZ);
    cudaFuncSetAttribute(gemm_kernel<2, CHUNK, NR, CHUNK / 32, 512, false>,
                         cudaFuncAttributeMaxDynamicSharedMemorySize, SMEMSZ);
    cudaFuncSetAttribute(gemm_kernel<2, CHUNK, NR, CHUNK / 32, 512, true>,
                         cudaFuncAttributeMaxDynamicSharedMemorySize, SMEMSZ);

    convert_feats<<<dim3(NR * KD / 4 / 256, 2), 256>>>(feat_p, feat_s);
    transpose_w<<<dim3(16, 16), dim3(32, 32)>>>(weight);
    transpose_vs<<<dim3(16, 256), dim3(32, 32)>>>(feat_s);

    // proj (1-term): M=8192 N=512 K=512   (reads Fp/Fs from S region, then dead)
    gemm_kernel<0, 512, 512, 16, 512, false><<<dim3(2, 64), NTHREADS, SMEMSZ>>>(
        Fp_hi, Wt_hi, Hp_hi, nullptr, 0);
    gemm_kernel<0, 512, 512, 16, 512, false><<<dim3(2, 64), NTHREADS, SMEMSZ>>>(
        Fs_hi, Wt_hi, Hs_hi, nullptr, 0);

    // chunk 0: S0 = relu(Hp @ Hs[0:4096]^T); C partial (unscaled)
    gemm_kernel<1, 512, 512, 16, CHUNK, false><<<dim3(CHUNK / 256, 64), NTHREADS, SMEMSZ>>>(
        Hp_hi, Hs_hi, S_hi, nullptr, 0);
    gemm_kernel<2, CHUNK, NR, CHUNK / 32, 512, false><<<dim3(2, 64), NTHREADS, SMEMSZ>>>(
        S_hi, Vt_hi, nullptr, out, 0);

    // chunk 1: S1; then reduce (all partials now exist); final C folds 1/fro
    gemm_kernel<1, 512, 512, 16, CHUNK, false><<<dim3(CHUNK / 256, 64), NTHREADS, SMEMSZ>>>(
        Hp_hi, Hs_hi + (size_t)CHUNK * 512, S_hi, nullptr, (CHUNK / 256) * 64);
    reduce_kernel<<<1, 1024>>>();
    gemm_kernel<2, CHUNK, NR, CHUNK / 32, 512, true><<<dim3(2, 64), NTHREADS, SMEMSZ>>>(
        S_hi, Vt_hi + CHUNK, nullptr, out, 0);
}